// round 8
// baseline (speedup 1.0000x reference)
#include <cuda_runtime.h>
#include <math.h>

#define CDIV(a,b) (((a)+(b)-1)/(b))

constexpr int NI     = 8;
constexpr int NANCH  = 10000;
constexpr int PRENMS = 1000;
constexpr int NROIS  = 200;

// ---- scratch layout (floats) ----
constexpr size_t O_C1  = 0;                constexpr size_t S_C1  = (size_t)NI*24*160*160;
constexpr size_t O_P1  = O_C1 + S_C1;      constexpr size_t S_P1  = (size_t)NI*24*80*80;
constexpr size_t O_C3  = O_P1 + S_P1;      constexpr size_t S_C3  = (size_t)NI*132*40*40;
constexpr size_t O_C4  = O_C3 + S_C3;      constexpr size_t S_C4  = (size_t)NI*264*20*20;
constexpr size_t O_C5  = O_C4 + S_C4;      constexpr size_t S_C5  = (size_t)NI*528*10*10;
constexpr size_t O_GLB = O_C5 + S_C5;      constexpr size_t S_GLB = (size_t)NI*528;
constexpr size_t O_GFC = O_GLB + S_GLB;    constexpr size_t S_GFC = (size_t)NI*245;
constexpr size_t O_CEM5= O_GFC + S_GFC;    constexpr size_t S_CEM5= (size_t)NI*245*100;
constexpr size_t O_FCEM= O_CEM5 + S_CEM5;  constexpr size_t S_FCEM= (size_t)NI*245*400;
constexpr size_t O_T   = O_FCEM + S_FCEM;  constexpr size_t S_T   = S_FCEM;
constexpr size_t O_FRPN= O_T + S_T;        constexpr size_t S_FRPN= (size_t)NI*256*400;
constexpr size_t O_CLS = O_FRPN + S_FRPN;  constexpr size_t S_CLS = (size_t)NI*50*400;
constexpr size_t O_REG = O_CLS + S_CLS;    constexpr size_t S_REG = (size_t)NI*100*400;
constexpr size_t O_FSAM= O_REG + S_REG;    constexpr size_t S_FSAM= S_FCEM;
constexpr size_t O_BOX = O_FSAM + S_FSAM;  constexpr size_t S_BOX = (size_t)NI*NANCH*4;
constexpr size_t O_BK  = O_BOX + S_BOX;    constexpr size_t S_BK  = (size_t)NI*PRENMS*4;
constexpr size_t O_ROI = O_BK + S_BK;      constexpr size_t S_ROI = (size_t)NI*NROIS*4;
constexpr size_t O_FROI= O_ROI + S_ROI;    constexpr size_t S_FROI= (size_t)245*NI*NROIS; // transposed [245][1600]
constexpr size_t O_H   = O_FROI + S_FROI;  constexpr size_t S_H   = (size_t)NI*NROIS*1024;
constexpr size_t O_PART= O_H + S_H;        constexpr size_t S_PART= (size_t)4*NI*264*400; // split-K partials (max: conv3)
constexpr size_t TOTAL = O_PART + S_PART;

__device__ float g_buf[TOTAL];
__device__ unsigned long long g_keys[(size_t)NI*NANCH];
__device__ unsigned int g_mask[(size_t)NI*1024*32];   // suppression bitmask [n][i][jword]

// =================== big tiled GEMM: 128x64 tile, 8x4/thread ===================
// MODE: 1 bias+relu, 4 relu + transposed store C[n][m], 5 raw partial store (split-K)
template<int MODE, bool TRANSA, bool CONV>
__global__ void __launch_bounds__(256)
gemm_big(const float* __restrict__ A, const float* __restrict__ B,
         const float* __restrict__ bias, float* __restrict__ C,
         int M, int K, int N, long sB, long sC,
         int Cin, int Hin, int Hout, int S, int kLen) {
    __shared__ float As[16][132];
    __shared__ float Bs[16][68];
    int nimg, spl;
    if (MODE == 5) { nimg = blockIdx.z / S; spl = blockIdx.z % S; }
    else           { nimg = blockIdx.z;     spl = 0; }
    int kStart = spl * kLen;
    int kEnd   = min(K, kStart + kLen);
    int m0 = blockIdx.y*128, n0 = blockIdx.x*64;
    const float* Bp = B + (long)nimg*sB;
    float* Cp = (MODE == 5) ? C + ((long)spl*NI + nimg)*M*N
                            : C + (long)nimg*sC;
    int tid = threadIdx.x;
    int tx = tid % 16, ty = tid / 16;   // tx: 4 cols, ty: 8 rows
    float acc[8][4] = {};
    for (int k0 = kStart; k0 < kEnd; k0 += 16) {
        if (!TRANSA) {
            int r = tid >> 1, c = (tid & 1) * 8;   // r: m 0..127, c: k base
            #pragma unroll
            for (int i = 0; i < 8; i++) {
                int mm = m0 + r, kk = k0 + c + i;
                As[c+i][r] = (mm < M && kk < kEnd) ? A[(long)mm*K + kk] : 0.f;
            }
        } else {
            int r = tid >> 4, c = (tid & 15) * 8;  // r: k, c: m base
            #pragma unroll
            for (int i = 0; i < 8; i++) {
                int kk = k0 + r, mm = m0 + c + i;
                As[r][c+i] = (mm < M && kk < kEnd) ? A[(long)kk*M + mm] : 0.f;
            }
        }
        if (CONV) {
            int r = tid >> 4, c = (tid & 15) * 4;
            int kk = k0 + r;
            bool kv = kk < kEnd;
            int ic = 0, ky = 0, kx = 0;
            if (kv) { ic = kk / 9; int rem = kk - ic*9; ky = rem / 3; kx = rem - ky*3; }
            #pragma unroll
            for (int i = 0; i < 4; i++) {
                int nn = n0 + c + i;
                float v = 0.f;
                if (kv && nn < N) {
                    int oy = nn / Hout, ox = nn - oy*Hout;
                    int iy = 2*oy + ky, ix = 2*ox + kx;
                    if (iy < Hin && ix < Hin)
                        v = Bp[((long)ic*Hin + iy)*Hin + ix];
                }
                Bs[r][c+i] = v;
            }
        } else {
            int r = tid >> 4, c = (tid & 15) * 4;
            #pragma unroll
            for (int i = 0; i < 4; i++) {
                int kk = k0 + r, nn = n0 + c + i;
                Bs[r][c+i] = (kk < kEnd && nn < N) ? Bp[(long)kk*N + nn] : 0.f;
            }
        }
        __syncthreads();
        #pragma unroll
        for (int kk = 0; kk < 16; kk++) {
            float4 a0 = *reinterpret_cast<const float4*>(&As[kk][ty*8]);
            float4 a1 = *reinterpret_cast<const float4*>(&As[kk][ty*8+4]);
            float4 bv = *reinterpret_cast<const float4*>(&Bs[kk][tx*4]);
            float a[8] = {a0.x, a0.y, a0.z, a0.w, a1.x, a1.y, a1.z, a1.w};
            float b[4] = {bv.x, bv.y, bv.z, bv.w};
            #pragma unroll
            for (int i = 0; i < 8; i++)
                #pragma unroll
                for (int j = 0; j < 4; j++)
                    acc[i][j] = fmaf(a[i], b[j], acc[i][j]);
        }
        __syncthreads();
    }
    #pragma unroll
    for (int i = 0; i < 8; i++) {
        int m = m0 + ty*8 + i;
        if (m >= M) continue;
        float bvl = (MODE == 5) ? 0.f : bias[m];
        #pragma unroll
        for (int j = 0; j < 4; j++) {
            int n = n0 + tx*4 + j;
            if (n >= N) continue;
            float s = acc[i][j] + bvl;
            if (MODE == 1) s = fmaxf(s, 0.f);
            if (MODE == 4) {
                s = fmaxf(s, 0.f);
                Cp[(long)n*M + m] = s;
            } else {
                Cp[(long)m*N + n] = s;
            }
        }
    }
}

// =================== small tiled GEMM: 64x64 tile, 4x4/thread ===================
// MODE: 0 bias, 1 bias+relu, 2 fsam: e1*sigmoid(s), 3 fcem adds
template<int MODE, bool CONV>
__global__ void __launch_bounds__(256)
gemm_tiled(const float* __restrict__ A, const float* __restrict__ B,
           const float* __restrict__ bias, float* __restrict__ C,
           int M, int K, int N, long sB, long sC,
           const float* __restrict__ e1, const float* __restrict__ e2,
           int Cin, int Hin, int Hout) {
    __shared__ float As[16][68];
    __shared__ float Bs[16][68];
    int nimg = blockIdx.z;
    int m0 = blockIdx.y*64, n0 = blockIdx.x*64;
    const float* Bp = B + (long)nimg*sB;
    float* Cp = C + (long)nimg*sC;
    int tid = threadIdx.x;
    int tx = tid % 16, ty = tid / 16;
    float acc[4][4] = {};
    for (int k0 = 0; k0 < K; k0 += 16) {
        {
            int r = tid >> 2, c = (tid & 3) * 4;
            #pragma unroll
            for (int i = 0; i < 4; i++) {
                int mm = m0 + r, kk = k0 + c + i;
                As[c+i][r] = (mm < M && kk < K) ? A[(long)mm*K + kk] : 0.f;
            }
        }
        if (CONV) {
            int r = tid >> 4, c = (tid & 15) * 4;
            int kk = k0 + r;
            bool kv = kk < K;
            int ic = 0, ky = 0, kx = 0;
            if (kv) { ic = kk / 9; int rem = kk - ic*9; ky = rem / 3; kx = rem - ky*3; }
            #pragma unroll
            for (int i = 0; i < 4; i++) {
                int nn = n0 + c + i;
                float v = 0.f;
                if (kv && nn < N) {
                    int oy = nn / Hout, ox = nn - oy*Hout;
                    int iy = 2*oy + ky, ix = 2*ox + kx;
                    if (iy < Hin && ix < Hin)
                        v = Bp[((long)ic*Hin + iy)*Hin + ix];
                }
                Bs[r][c+i] = v;
            }
        } else {
            int r = tid >> 4, c = (tid & 15) * 4;
            #pragma unroll
            for (int i = 0; i < 4; i++) {
                int kk = k0 + r, nn = n0 + c + i;
                Bs[r][c+i] = (kk < K && nn < N) ? Bp[(long)kk*N + nn] : 0.f;
            }
        }
        __syncthreads();
        #pragma unroll
        for (int kk = 0; kk < 16; kk++) {
            float4 av = *reinterpret_cast<const float4*>(&As[kk][ty*4]);
            float4 bv = *reinterpret_cast<const float4*>(&Bs[kk][tx*4]);
            float a[4] = {av.x, av.y, av.z, av.w};
            float b[4] = {bv.x, bv.y, bv.z, bv.w};
            #pragma unroll
            for (int i = 0; i < 4; i++)
                #pragma unroll
                for (int j = 0; j < 4; j++)
                    acc[i][j] = fmaf(a[i], b[j], acc[i][j]);
        }
        __syncthreads();
    }
    #pragma unroll
    for (int i = 0; i < 4; i++) {
        int m = m0 + ty*4 + i;
        if (m >= M) continue;
        float bv = bias[m];
        #pragma unroll
        for (int j = 0; j < 4; j++) {
            int n = n0 + tx*4 + j;
            if (n >= N) continue;
            float s = acc[i][j] + bv;
            if (MODE == 1) s = fmaxf(s, 0.f);
            else if (MODE == 2) {
                s = e1[(long)nimg*sC + (long)m*N + n] * (1.f/(1.f + expf(-s)));
            } else if (MODE == 3) {
                int y = n / 20, x = n % 20;
                s += e1[nimg*245 + m] + e2[((long)nimg*245 + m)*100 + (y/2)*10 + (x/2)];
            }
            Cp[(long)m*N + n] = s;
        }
    }
}

// ---- split-K reduction: out = relu(bias + sum_s partial) ----
__global__ void reduce_relu_kernel(const float* __restrict__ partial, const float* __restrict__ bias,
                                   float* __restrict__ out, int S, int M, int N, long sC) {
    int t = blockIdx.x*blockDim.x + threadIdx.x;
    int total = NI*M*N;
    if (t >= total) return;
    int nimg = t / (M*N);
    int mn   = t % (M*N);
    int m    = mn / N;
    float s = bias[m];
    for (int si = 0; si < S; si++)
        s += partial[((long)si*NI + nimg)*M*N + mn];
    out[(long)nimg*sC + mn] = fmaxf(s, 0.f);
}

// =================== 3x3 stride-2 maxpool SAME ===================
__global__ void maxpool3s2(const float* __restrict__ in, float* __restrict__ out,
                           int C, int Hin, int Hout) {
    int t = blockIdx.x*blockDim.x + threadIdx.x;
    int total = NI*C*Hout*Hout;
    if (t >= total) return;
    int ox = t % Hout;
    int oy = (t / Hout) % Hout;
    int nc = t / (Hout*Hout);
    const float* ip = in + (size_t)nc*Hin*Hin;
    float m = -INFINITY;
    #pragma unroll
    for (int ky = 0; ky < 3; ky++) {
        int iy = 2*oy + ky;
        if (iy >= Hin) continue;
        #pragma unroll
        for (int kx = 0; kx < 3; kx++) {
            int ix = 2*ox + kx;
            if (ix >= Hin) continue;
            m = fmaxf(m, ip[iy*Hin+ix]);
        }
    }
    out[t] = m;
}

__global__ void gap_kernel(const float* __restrict__ c5, float* __restrict__ glb) {
    int t = blockIdx.x*blockDim.x + threadIdx.x;
    if (t >= NI*528) return;
    const float* p = c5 + (size_t)t*100;
    float s = 0.f;
    for (int i = 0; i < 100; i++) s += p[i];
    glb[t] = s / 100.f;
}

__global__ void gfc_kernel(const float* __restrict__ glb, const float* __restrict__ wg,
                           const float* __restrict__ bg, float* __restrict__ gfc) {
    int t = blockIdx.x*blockDim.x + threadIdx.x;
    if (t >= NI*245) return;
    int k = t % 245, n = t / 245;
    float s = bg[k];
    const float* g = glb + n*528;
    for (int c = 0; c < 528; c++) s += g[c] * wg[c*245 + k];
    gfc[t] = s;
}

// ---- depthwise 5x5 SAME + relu ----
__global__ void dw5_kernel(const float* __restrict__ in, const float* __restrict__ w,
                           const float* __restrict__ bias, float* __restrict__ out) {
    int t = blockIdx.x*blockDim.x + threadIdx.x;
    int total = NI*245*400;
    if (t >= total) return;
    int p = t % 400;
    int k = (t / 400) % 245;
    int y = p / 20, x = p % 20;
    const float* ip = in + (size_t)(t/400)*400;
    const float* wk = w + k*25;
    float s = bias[k];
    #pragma unroll
    for (int ky = 0; ky < 5; ky++) {
        int iy = y - 2 + ky;
        if (iy < 0 || iy >= 20) continue;
        #pragma unroll
        for (int kx = 0; kx < 5; kx++) {
            int ix = x - 2 + kx;
            if (ix < 0 || ix >= 20) continue;
            s += ip[iy*20+ix] * wk[ky*5+kx];
        }
    }
    out[t] = fmaxf(s, 0.f);
}

// ---- scores + decoded boxes + sort keys ----
__global__ void scorebox_kernel(const float* __restrict__ clsmap, const float* __restrict__ regmap,
                                float* __restrict__ boxes, unsigned long long* __restrict__ keys) {
    int t = blockIdx.x*blockDim.x + threadIdx.x;
    if (t >= NI*NANCH) return;
    int i = t % NANCH;
    int n = t / NANCH;
    int a = i % 25;
    int x = (i / 25) % 20;
    int y = i / 500;
    int p = y*20 + x;
    const float* cm = clsmap + (size_t)n*50*400;
    float c0 = cm[(a*2  )*400 + p];
    float c1 = cm[(a*2+1)*400 + p];
    float score = 1.f / (1.f + expf(c0 - c1));
    const float* rm = regmap + (size_t)n*100*400;
    float d0 = rm[(a*4  )*400 + p];
    float d1 = rm[(a*4+1)*400 + p];
    float d2 = rm[(a*4+2)*400 + p];
    float d3 = rm[(a*4+3)*400 + p];
    const float scales[5] = {32.f, 64.f, 128.f, 256.f, 512.f};
    const float ratios[5] = {0.5f, 0.75f, 1.0f, 4.0f/3.0f, 2.0f};
    int si = a / 5, ri = a % 5;
    float sq = sqrtf(ratios[ri]);
    float aw = scales[si] / sq;
    float ah = scales[si] * sq;
    float acx = (x + 0.5f) * 16.f;
    float acy = (y + 0.5f) * 16.f;
    float cx = d0*aw + acx;
    float cy = d1*ah + acy;
    float w  = expf(d2) * aw;
    float h  = expf(d3) * ah;
    float* b = boxes + ((size_t)n*NANCH + i)*4;
    b[0] = fminf(fmaxf(cx - 0.5f*w, 0.f), 319.f);
    b[1] = fminf(fmaxf(cy - 0.5f*h, 0.f), 319.f);
    b[2] = fminf(fmaxf(cx + 0.5f*w, 0.f), 319.f);
    b[3] = fminf(fmaxf(cy + 0.5f*h, 0.f), 319.f);
    unsigned sb = __float_as_uint(score);  // score > 0 -> bit-monotone
    keys[t] = ((unsigned long long)sb << 32) | (unsigned long long)(0xFFFFFFFFu - (unsigned)i);
}

// ---- exact top-1000 per image: 64-bit radix select + bitonic sort of 1024 ----
__global__ void __launch_bounds__(1024)
topk_kernel(const unsigned long long* __restrict__ keys,
            const float* __restrict__ boxes, float* __restrict__ bk) {
    __shared__ unsigned int hist[256];
    __shared__ unsigned long long sh_prefix;
    __shared__ int sh_need;
    __shared__ unsigned int sh_cnt;
    __shared__ unsigned long long sk[1024];
    int n = blockIdx.x;
    int tid = threadIdx.x;
    const unsigned long long* kp = keys + (size_t)n*NANCH;

    if (tid == 0) { sh_prefix = 0ull; sh_need = PRENMS; sh_cnt = 0u; }
    __syncthreads();

    for (int shift = 56; shift >= 0; shift -= 8) {
        if (tid < 256) hist[tid] = 0u;
        __syncthreads();
        unsigned long long prefmask = (shift == 56) ? 0ull : (~0ull << (shift + 8));
        unsigned long long pref = sh_prefix;
        for (int i = tid; i < NANCH; i += 1024) {
            unsigned long long k = kp[i];
            if ((k & prefmask) == pref)
                atomicAdd(&hist[(unsigned)(k >> shift) & 255u], 1u);
        }
        __syncthreads();
        if (tid == 0) {
            int need = sh_need;
            unsigned cum = 0;
            int d = 255;
            for (; d >= 0; d--) { cum += hist[d]; if ((int)cum >= need) break; }
            sh_need = need - (int)(cum - hist[d]);
            sh_prefix = pref | ((unsigned long long)d << shift);
        }
        __syncthreads();
    }
    unsigned long long T = sh_prefix;

    if (tid < 24) sk[1000 + tid] = 0ull;
    for (int i = tid; i < NANCH; i += 1024) {
        unsigned long long k = kp[i];
        if (k >= T) sk[atomicAdd(&sh_cnt, 1u)] = k;
    }
    __syncthreads();

    for (int size = 2; size <= 1024; size <<= 1) {
        for (int stride = size >> 1; stride > 0; stride >>= 1) {
            if (tid < 512) {
                int lo = ((tid & ~(stride-1)) << 1) | (tid & (stride-1));
                int hi = lo + stride;
                unsigned long long a = sk[lo], c = sk[hi];
                bool desc = ((lo & size) == 0);
                if (desc ? (a < c) : (a > c)) { sk[lo] = c; sk[hi] = a; }
            }
            __syncthreads();
        }
    }

    if (tid < PRENMS) {
        unsigned idx = 0xFFFFFFFFu - (unsigned)(sk[tid] & 0xFFFFFFFFull);
        const float* src = boxes + ((size_t)n*NANCH + idx)*4;
        float* dst = bk + ((size_t)n*PRENMS + tid)*4;
        dst[0] = src[0]; dst[1] = src[1]; dst[2] = src[2]; dst[3] = src[3];
    }
}

// ---- suppression bitmask ----
__global__ void __launch_bounds__(256)
nms_mask_kernel(const float* __restrict__ bk, unsigned int* __restrict__ mask) {
    __shared__ float4 box[PRENMS];
    __shared__ float  area[PRENMS];
    int n = blockIdx.x;
    int i0 = blockIdx.y * 8;
    int tid = threadIdx.x;
    const float* b = bk + (size_t)n*PRENMS*4;
    for (int i = tid; i < PRENMS; i += 256) {
        float x1 = b[i*4], y1 = b[i*4+1], x2 = b[i*4+2], y2 = b[i*4+3];
        box[i] = make_float4(x1, y1, x2, y2);
        area[i] = (x2-x1)*(y2-y1);
    }
    __syncthreads();
    int w  = tid & 31;
    int il = tid >> 5;
    int i = i0 + il;
    if (i >= PRENMS) return;
    float4 bi = box[i];
    float ai = area[i];
    unsigned m = 0u;
    int jbase = w * 32;
    #pragma unroll 4
    for (int bbit = 0; bbit < 32; bbit++) {
        int j = jbase + bbit;
        if (j > i && j < PRENMS) {
            float ix1 = fmaxf(bi.x, box[j].x);
            float iy1 = fmaxf(bi.y, box[j].y);
            float ix2 = fminf(bi.z, box[j].z);
            float iy2 = fminf(bi.w, box[j].w);
            float inter = fmaxf(ix2-ix1, 0.f) * fmaxf(iy2-iy1, 0.f);
            float iou = inter / (ai + area[j] - inter + 1e-9f);
            if (iou > 0.7f) m |= (1u << bbit);
        }
    }
    mask[((size_t)n*1024 + i)*32 + w] = m;
}

// ---- single-warp NMS scan + stable partition -> 200 rois ----
__global__ void __launch_bounds__(32)
nms_scan_kernel(const unsigned int* __restrict__ mask, const float* __restrict__ bk,
                float* __restrict__ rois, float* __restrict__ out_rois) {
    __shared__ unsigned char keep[PRENMS];
    __shared__ int order[NROIS];
    int n = blockIdx.x;
    int lane = threadIdx.x;
    const unsigned int* mp = mask + (size_t)n*1024*32;
    unsigned removed = 0u;
    unsigned next_m = mp[0*32 + lane];
    for (int i = 0; i < PRENMS; i++) {
        unsigned m = next_m;
        if (i + 1 < PRENMS) next_m = mp[(i+1)*32 + lane];
        unsigned rw = __shfl_sync(0xFFFFFFFFu, removed, i >> 5);
        bool keep_i = ((rw >> (i & 31)) & 1u) == 0u;
        if (keep_i) removed |= m;
        if (lane == 0) keep[i] = keep_i ? 1 : 0;
    }
    __syncwarp();
    if (lane == 0) {
        int c = 0;
        for (int i = 0; i < PRENMS && c < NROIS; i++) if (keep[i])  order[c++] = i;
        for (int i = 0; i < PRENMS && c < NROIS; i++) if (!keep[i]) order[c++] = i;
    }
    __syncwarp();
    const float* b = bk + (size_t)n*PRENMS*4;
    for (int r = lane; r < NROIS; r += 32) {
        int idx = order[r];
        float x1 = b[idx*4], y1 = b[idx*4+1], x2 = b[idx*4+2], y2 = b[idx*4+3];
        float* dst = rois + ((size_t)n*NROIS + r)*4;
        dst[0] = x1; dst[1] = y1; dst[2] = x2; dst[3] = y2;
        float* o = out_rois + ((size_t)n*NROIS + r)*4;
        o[0] = x1; o[1] = y1; o[2] = x2; o[3] = y2;
    }
}

// ---- PSRoI pooling: stores TRANSPOSED froiT[c][n*200+r] for fc1 GEMM ----
__global__ void psroi_kernel(const float* __restrict__ fsam, const float* __restrict__ rois,
                             float* __restrict__ froiT) {
    int t = blockIdx.x*blockDim.x + threadIdx.x;
    int total = NI*NROIS*245;
    if (t >= total) return;
    int c = t % 245;
    int r = (t / 245) % NROIS;
    int n = t / (245*NROIS);
    const float* ro = rois + ((size_t)n*NROIS + r)*4;
    float x1 = ro[0] * (1.f/16.f), y1 = ro[1] * (1.f/16.f);
    float x2 = ro[2] * (1.f/16.f), y2 = ro[3] * (1.f/16.f);
    float bw = fmaxf(x2-x1, 0.1f) * (1.f/7.f);
    float bh = fmaxf(y2-y1, 0.1f) * (1.f/7.f);
    int ij = c % 49;
    int i = ij / 7, j = ij % 7;
    float sx = x1 + (j + 0.5f) * bw;
    float sy = y1 + (i + 0.5f) * bh;
    float x = fminf(fmaxf(sx, 0.f), 19.f);
    float y = fminf(fmaxf(sy, 0.f), 19.f);
    int y0 = min(max((int)floorf(y), 0), 18);
    int x0 = min(max((int)floorf(x), 0), 18);
    float wy = y - (float)y0;
    float wx = x - (float)x0;
    const float* f = fsam + ((size_t)n*245 + c)*400;
    float v00 = f[y0*20 + x0],     v01 = f[y0*20 + x0 + 1];
    float v10 = f[(y0+1)*20 + x0], v11 = f[(y0+1)*20 + x0 + 1];
    float v = v00*(1.f-wy)*(1.f-wx) + v01*(1.f-wy)*wx + v10*wy*(1.f-wx) + v11*wy*wx;
    froiT[(size_t)c*(NI*NROIS) + (size_t)n*NROIS + r] = v;
}

// ---- FC2 heads: one warp per (row, output) ----
__global__ void __launch_bounds__(256)
fc2_warp(const float* __restrict__ h, const float* __restrict__ cfw,
         const float* __restrict__ cfb, const float* __restrict__ rfw,
         const float* __restrict__ rfb, float* __restrict__ out_cls,
         float* __restrict__ out_reg) {
    int w = (blockIdx.x*blockDim.x + threadIdx.x) >> 5;
    int lane = threadIdx.x & 31;
    if (w >= NI*NROIS*25) return;
    int m = w % 25;
    int row = w / 25;
    const float* hr = h + (size_t)row*1024;
    float s = 0.f;
    if (m < 21) {
        for (int k = lane; k < 1024; k += 32) s = fmaf(hr[k], cfw[k*21 + m], s);
    } else {
        int mm = m - 21;
        for (int k = lane; k < 1024; k += 32) s = fmaf(hr[k], rfw[k*4 + mm], s);
    }
    #pragma unroll
    for (int o = 16; o > 0; o >>= 1) s += __shfl_down_sync(0xFFFFFFFFu, s, o);
    if (lane == 0) {
        if (m < 21) out_cls[row*21 + m] = s + cfb[m];
        else        out_reg[row*4 + (m-21)] = s + rfb[m-21];
    }
}

extern "C" void kernel_launch(void* const* d_in, const int* in_sizes, int n_in,
                              void* d_out, int out_size) {
    const float* x      = (const float*)d_in[0];
    const float* w1     = (const float*)d_in[1];
    const float* b1     = (const float*)d_in[2];
    const float* w2     = (const float*)d_in[3];
    const float* b2     = (const float*)d_in[4];
    const float* w3     = (const float*)d_in[5];
    const float* b3     = (const float*)d_in[6];
    const float* w4     = (const float*)d_in[7];
    const float* b4     = (const float*)d_in[8];
    const float* cem_w4 = (const float*)d_in[9];
    const float* cem_b4 = (const float*)d_in[10];
    const float* cem_w5 = (const float*)d_in[11];
    const float* cem_b5 = (const float*)d_in[12];
    const float* cem_wg = (const float*)d_in[13];
    const float* cem_bg = (const float*)d_in[14];
    const float* rpn_dw = (const float*)d_in[15];
    const float* rpn_dwb= (const float*)d_in[16];
    const float* rpn_pw = (const float*)d_in[17];
    const float* rpn_pwb= (const float*)d_in[18];
    const float* cls_w  = (const float*)d_in[19];
    const float* cls_b  = (const float*)d_in[20];
    const float* reg_w  = (const float*)d_in[21];
    const float* reg_b  = (const float*)d_in[22];
    const float* sam_w  = (const float*)d_in[23];
    const float* sam_b  = (const float*)d_in[24];
    const float* fc_w   = (const float*)d_in[25];
    const float* fc_b   = (const float*)d_in[26];
    const float* cls_fw = (const float*)d_in[27];
    const float* cls_fb = (const float*)d_in[28];
    const float* reg_fw = (const float*)d_in[29];
    const float* reg_fb = (const float*)d_in[30];
    float* out = (float*)d_out;

    float* buf = nullptr;
    cudaGetSymbolAddress((void**)&buf, g_buf);
    unsigned long long* keys = nullptr;
    cudaGetSymbolAddress((void**)&keys, g_keys);
    unsigned int* mask = nullptr;
    cudaGetSymbolAddress((void**)&mask, g_mask);

    const int TB = 256;
    float* part = buf + O_PART;

    // ---- conv1: 3->24, 320->160 (implicit GEMM, small tile: M=24) ----
    gemm_tiled<1,true><<<dim3(CDIV(25600,64), 1, NI), 256>>>(
        w1, x, b1, buf+O_C1, 24, 27, 25600, (long)3*320*320, (long)24*25600,
        nullptr, nullptr, 3, 320, 160);
    maxpool3s2<<<CDIV(NI*24*80*80, TB), TB>>>(buf+O_C1, buf+O_P1, 24, 160, 80);
    // ---- conv2: 24->132, 80->40 (implicit GEMM, big tile) ----
    gemm_big<1,false,true><<<dim3(CDIV(1600,64), CDIV(132,128), NI), 256>>>(
        w2, buf+O_P1, b2, buf+O_C3, 132, 216, 1600, (long)24*80*80, (long)132*1600,
        24, 80, 40, 1, 216);
    // ---- conv3: 132->264, 40->20 (implicit GEMM, big tile, split-K=4) ----
    gemm_big<5,false,true><<<dim3(CDIV(400,64), CDIV(264,128), NI*4), 256>>>(
        w3, buf+O_C3, nullptr, part, 264, 1188, 400, (long)132*40*40, 0,
        132, 40, 20, 4, 297);
    reduce_relu_kernel<<<CDIV(NI*264*400, TB), TB>>>(part, b3, buf+O_C4, 4, 264, 400, (long)264*400);
    // ---- conv4: 264->528, 20->10 (implicit GEMM, big tile, split-K=4) ----
    gemm_big<5,false,true><<<dim3(CDIV(100,64), CDIV(528,128), NI*4), 256>>>(
        w4, buf+O_C4, nullptr, part, 528, 2376, 100, (long)264*20*20, 0,
        264, 20, 10, 4, 594);
    reduce_relu_kernel<<<CDIV(NI*528*100, TB), TB>>>(part, b4, buf+O_C5, 4, 528, 100, (long)528*100);

    // ---- CEM ----
    gap_kernel<<<CDIV(NI*528, TB), TB>>>(buf+O_C5, buf+O_GLB);
    gfc_kernel<<<CDIV(NI*245, TB), TB>>>(buf+O_GLB, cem_wg, cem_bg, buf+O_GFC);
    gemm_tiled<0,false><<<dim3(CDIV(100,64), CDIV(245,64), NI), 256>>>(
        cem_w5, buf+O_C5, cem_b5, buf+O_CEM5, 245, 528, 100,
        (long)528*100, (long)245*100, nullptr, nullptr, 0, 0, 0);
    gemm_tiled<3,false><<<dim3(CDIV(400,64), CDIV(245,64), NI), 256>>>(
        cem_w4, buf+O_C4, cem_b4, buf+O_FCEM, 245, 264, 400,
        (long)264*400, (long)245*400, buf+O_GFC, buf+O_CEM5, 0, 0, 0);

    // ---- RPN ----
    dw5_kernel<<<CDIV(NI*245*400, TB), TB>>>(buf+O_FCEM, rpn_dw, rpn_dwb, buf+O_T);
    gemm_tiled<1,false><<<dim3(CDIV(400,64), CDIV(256,64), NI), 256>>>(
        rpn_pw, buf+O_T, rpn_pwb, buf+O_FRPN, 256, 245, 400,
        (long)245*400, (long)256*400, nullptr, nullptr, 0, 0, 0);
    gemm_tiled<0,false><<<dim3(CDIV(400,64), CDIV(50,64), NI), 256>>>(
        cls_w, buf+O_FRPN, cls_b, buf+O_CLS, 50, 256, 400,
        (long)256*400, (long)50*400, nullptr, nullptr, 0, 0, 0);
    gemm_tiled<0,false><<<dim3(CDIV(400,64), CDIV(100,64), NI), 256>>>(
        reg_w, buf+O_FRPN, reg_b, buf+O_REG, 100, 256, 400,
        (long)256*400, (long)100*400, nullptr, nullptr, 0, 0, 0);
    gemm_tiled<2,false><<<dim3(CDIV(400,64), CDIV(245,64), NI), 256>>>(
        sam_w, buf+O_FRPN, sam_b, buf+O_FSAM, 245, 256, 400,
        (long)256*400, (long)245*400, buf+O_FCEM, nullptr, 0, 0, 0);

    // ---- proposals ----
    scorebox_kernel<<<CDIV(NI*NANCH, TB), TB>>>(buf+O_CLS, buf+O_REG, buf+O_BOX, keys);
    topk_kernel<<<NI, 1024>>>(keys, buf+O_BOX, buf+O_BK);
    nms_mask_kernel<<<dim3(NI, 125), 256>>>(buf+O_BK, mask);
    nms_scan_kernel<<<NI, 32>>>(mask, buf+O_BK, buf+O_ROI,
                                out + (size_t)NI*NROIS*21 + (size_t)NI*NROIS*4);

    // ---- head ----
    psroi_kernel<<<CDIV(NI*NROIS*245, TB), TB>>>(buf+O_FSAM, buf+O_ROI, buf+O_FROI);
    gemm_big<4,true,false><<<dim3(CDIV(NI*NROIS,64), CDIV(1024,128), 1), 256>>>(
        fc_w, buf+O_FROI, fc_b, buf+O_H, 1024, 245, NI*NROIS, 0, 0,
        0, 0, 0, 1, 245);
    fc2_warp<<<CDIV(NI*NROIS*25*32, TB), TB>>>(buf+O_H, cls_fw, cls_fb, reg_fw, reg_fb,
                                               out, out + (size_t)NI*NROIS*21);
}

// round 10
// speedup vs baseline: 1.0296x; 1.0296x over previous
#include <cuda_runtime.h>
#include <math.h>

#define CDIV(a,b) (((a)+(b)-1)/(b))

constexpr int NI     = 8;
constexpr int NANCH  = 10000;
constexpr int PRENMS = 1000;
constexpr int NROIS  = 200;

// ---- scratch layout (floats) ----
constexpr size_t O_C1  = 0;                constexpr size_t S_C1  = (size_t)NI*24*160*160;
constexpr size_t O_P1  = O_C1 + S_C1;      constexpr size_t S_P1  = (size_t)NI*24*80*80;
constexpr size_t O_C3  = O_P1 + S_P1;      constexpr size_t S_C3  = (size_t)NI*132*40*40;
constexpr size_t O_C4  = O_C3 + S_C3;      constexpr size_t S_C4  = (size_t)NI*264*20*20;
constexpr size_t O_C5  = O_C4 + S_C4;      constexpr size_t S_C5  = (size_t)NI*528*10*10;
constexpr size_t O_GLB = O_C5 + S_C5;      constexpr size_t S_GLB = (size_t)NI*528;
constexpr size_t O_GFC = O_GLB + S_GLB;    constexpr size_t S_GFC = (size_t)NI*245;
constexpr size_t O_CEM5= O_GFC + S_GFC;    constexpr size_t S_CEM5= (size_t)NI*245*100;
constexpr size_t O_FCEM= O_CEM5 + S_CEM5;  constexpr size_t S_FCEM= (size_t)NI*245*400;
constexpr size_t O_T   = O_FCEM + S_FCEM;  constexpr size_t S_T   = S_FCEM;
constexpr size_t O_FRPN= O_T + S_T;        constexpr size_t S_FRPN= (size_t)NI*256*400;
constexpr size_t O_CLS = O_FRPN + S_FRPN;  constexpr size_t S_CLS = (size_t)NI*50*400;
constexpr size_t O_REG = O_CLS + S_CLS;    constexpr size_t S_REG = (size_t)NI*100*400;
constexpr size_t O_FSAM= O_REG + S_REG;    constexpr size_t S_FSAM= S_FCEM;
constexpr size_t O_BOX = O_FSAM + S_FSAM;  constexpr size_t S_BOX = (size_t)NI*NANCH*4;
constexpr size_t O_BK  = O_BOX + S_BOX;    constexpr size_t S_BK  = (size_t)NI*PRENMS*4;
constexpr size_t O_ROI = O_BK + S_BK;      constexpr size_t S_ROI = (size_t)NI*NROIS*4;
constexpr size_t O_FROI= O_ROI + S_ROI;    constexpr size_t S_FROI= (size_t)245*NI*NROIS; // transposed [245][1600]
constexpr size_t O_H   = O_FROI + S_FROI;  constexpr size_t S_H   = (size_t)NI*NROIS*1024;
constexpr size_t O_PART= O_H + S_H;        constexpr size_t S_PART= (size_t)4*NI*264*400; // split-K partials (max: conv3)
constexpr size_t TOTAL = O_PART + S_PART;

__device__ float g_buf[TOTAL];
__device__ unsigned long long g_keys[(size_t)NI*NANCH];
__device__ unsigned int g_mask[(size_t)NI*1024*32];   // suppression bitmask [n][i][jword]

// =================== fat-thread GEMM: 64x64 tile, 128 threads, 8x4/thread ===================
// MODE: 1 bias+relu, 4 relu + transposed store C[n][m], 5 raw partial store (split-K)
template<int MODE, bool TRANSA, bool CONV>
__global__ void __launch_bounds__(128)
gemm_fat(const float* __restrict__ A, const float* __restrict__ B,
         const float* __restrict__ bias, float* __restrict__ C,
         int M, int K, int N, long sB, long sC,
         int Cin, int Hin, int Hout, int S, int kLen) {
    __shared__ float As[16][68];
    __shared__ float Bs[16][68];
    int nimg, spl;
    if (MODE == 5) { nimg = blockIdx.z / S; spl = blockIdx.z % S; }
    else           { nimg = blockIdx.z;     spl = 0; }
    int kStart = spl * kLen;
    int kEnd   = min(K, kStart + kLen);
    int m0 = blockIdx.y*64, n0 = blockIdx.x*64;
    const float* Bp = B + (long)nimg*sB;
    float* Cp = (MODE == 5) ? C + ((long)spl*NI + nimg)*M*N
                            : C + (long)nimg*sC;
    int tid = threadIdx.x;
    int tx = tid & 15, ty = tid >> 4;   // tx: 4 n-cols, ty: 8 m-rows
    float acc[8][4] = {};
    for (int k0 = kStart; k0 < kEnd; k0 += 16) {
        if (!TRANSA) {
            int r = tid >> 1, c = (tid & 1) * 8;   // r: m 0..63, c: k base
            #pragma unroll
            for (int i = 0; i < 8; i++) {
                int mm = m0 + r, kk = k0 + c + i;
                As[c+i][r] = (mm < M && kk < kEnd) ? A[(long)mm*K + kk] : 0.f;
            }
        } else {
            int r = tid >> 3, c = (tid & 7) * 8;   // r: k 0..15, c: m base
            #pragma unroll
            for (int i = 0; i < 8; i++) {
                int kk = k0 + r, mm = m0 + c + i;
                As[r][c+i] = (mm < M && kk < kEnd) ? A[(long)kk*M + mm] : 0.f;
            }
        }
        if (CONV) {
            int r = tid >> 3, c = (tid & 7) * 8;
            int kk = k0 + r;
            bool kv = kk < kEnd;
            int ic = 0, ky = 0, kx = 0;
            if (kv) { ic = kk / 9; int rem = kk - ic*9; ky = rem / 3; kx = rem - ky*3; }
            #pragma unroll
            for (int i = 0; i < 8; i++) {
                int nn = n0 + c + i;
                float v = 0.f;
                if (kv && nn < N) {
                    int oy = nn / Hout, ox = nn - oy*Hout;
                    int iy = 2*oy + ky, ix = 2*ox + kx;
                    if (iy < Hin && ix < Hin)
                        v = Bp[((long)ic*Hin + iy)*Hin + ix];
                }
                Bs[r][c+i] = v;
            }
        } else {
            int r = tid >> 3, c = (tid & 7) * 8;
            #pragma unroll
            for (int i = 0; i < 8; i++) {
                int kk = k0 + r, nn = n0 + c + i;
                Bs[r][c+i] = (kk < kEnd && nn < N) ? Bp[(long)kk*N + nn] : 0.f;
            }
        }
        __syncthreads();
        #pragma unroll
        for (int kk = 0; kk < 16; kk++) {
            float4 a0 = *reinterpret_cast<const float4*>(&As[kk][ty*8]);
            float4 a1 = *reinterpret_cast<const float4*>(&As[kk][ty*8+4]);
            float4 bv = *reinterpret_cast<const float4*>(&Bs[kk][tx*4]);
            float a[8] = {a0.x, a0.y, a0.z, a0.w, a1.x, a1.y, a1.z, a1.w};
            float b[4] = {bv.x, bv.y, bv.z, bv.w};
            #pragma unroll
            for (int i = 0; i < 8; i++)
                #pragma unroll
                for (int j = 0; j < 4; j++)
                    acc[i][j] = fmaf(a[i], b[j], acc[i][j]);
        }
        __syncthreads();
    }
    #pragma unroll
    for (int i = 0; i < 8; i++) {
        int m = m0 + ty*8 + i;
        if (m >= M) continue;
        float bvl = (MODE == 5) ? 0.f : bias[m];
        #pragma unroll
        for (int j = 0; j < 4; j++) {
            int n = n0 + tx*4 + j;
            if (n >= N) continue;
            float s = acc[i][j] + bvl;
            if (MODE == 1) s = fmaxf(s, 0.f);
            if (MODE == 4) {
                s = fmaxf(s, 0.f);
                Cp[(long)n*M + m] = s;
            } else {
                Cp[(long)m*N + n] = s;
            }
        }
    }
}

// =================== small tiled GEMM: 64x64 tile, 256 thr, 4x4/thread ===================
// MODE: 0 bias, 1 bias+relu, 2 fsam: e1*sigmoid(s), 3 fcem adds
template<int MODE, bool CONV>
__global__ void __launch_bounds__(256)
gemm_tiled(const float* __restrict__ A, const float* __restrict__ B,
           const float* __restrict__ bias, float* __restrict__ C,
           int M, int K, int N, long sB, long sC,
           const float* __restrict__ e1, const float* __restrict__ e2,
           int Cin, int Hin, int Hout) {
    __shared__ float As[16][68];
    __shared__ float Bs[16][68];
    int nimg = blockIdx.z;
    int m0 = blockIdx.y*64, n0 = blockIdx.x*64;
    const float* Bp = B + (long)nimg*sB;
    float* Cp = C + (long)nimg*sC;
    int tid = threadIdx.x;
    int tx = tid % 16, ty = tid / 16;
    float acc[4][4] = {};
    for (int k0 = 0; k0 < K; k0 += 16) {
        {
            int r = tid >> 2, c = (tid & 3) * 4;
            #pragma unroll
            for (int i = 0; i < 4; i++) {
                int mm = m0 + r, kk = k0 + c + i;
                As[c+i][r] = (mm < M && kk < K) ? A[(long)mm*K + kk] : 0.f;
            }
        }
        if (CONV) {
            int r = tid >> 4, c = (tid & 15) * 4;
            int kk = k0 + r;
            bool kv = kk < K;
            int ic = 0, ky = 0, kx = 0;
            if (kv) { ic = kk / 9; int rem = kk - ic*9; ky = rem / 3; kx = rem - ky*3; }
            #pragma unroll
            for (int i = 0; i < 4; i++) {
                int nn = n0 + c + i;
                float v = 0.f;
                if (kv && nn < N) {
                    int oy = nn / Hout, ox = nn - oy*Hout;
                    int iy = 2*oy + ky, ix = 2*ox + kx;
                    if (iy < Hin && ix < Hin)
                        v = Bp[((long)ic*Hin + iy)*Hin + ix];
                }
                Bs[r][c+i] = v;
            }
        } else {
            int r = tid >> 4, c = (tid & 15) * 4;
            #pragma unroll
            for (int i = 0; i < 4; i++) {
                int kk = k0 + r, nn = n0 + c + i;
                Bs[r][c+i] = (kk < K && nn < N) ? Bp[(long)kk*N + nn] : 0.f;
            }
        }
        __syncthreads();
        #pragma unroll
        for (int kk = 0; kk < 16; kk++) {
            float4 av = *reinterpret_cast<const float4*>(&As[kk][ty*4]);
            float4 bv = *reinterpret_cast<const float4*>(&Bs[kk][tx*4]);
            float a[4] = {av.x, av.y, av.z, av.w};
            float b[4] = {bv.x, bv.y, bv.z, bv.w};
            #pragma unroll
            for (int i = 0; i < 4; i++)
                #pragma unroll
                for (int j = 0; j < 4; j++)
                    acc[i][j] = fmaf(a[i], b[j], acc[i][j]);
        }
        __syncthreads();
    }
    #pragma unroll
    for (int i = 0; i < 4; i++) {
        int m = m0 + ty*4 + i;
        if (m >= M) continue;
        float bv = bias[m];
        #pragma unroll
        for (int j = 0; j < 4; j++) {
            int n = n0 + tx*4 + j;
            if (n >= N) continue;
            float s = acc[i][j] + bv;
            if (MODE == 1) s = fmaxf(s, 0.f);
            else if (MODE == 2) {
                s = e1[(long)nimg*sC + (long)m*N + n] * (1.f/(1.f + expf(-s)));
            } else if (MODE == 3) {
                int y = n / 20, x = n % 20;
                s += e1[nimg*245 + m] + e2[((long)nimg*245 + m)*100 + (y/2)*10 + (x/2)];
            }
            Cp[(long)m*N + n] = s;
        }
    }
}

// ---- split-K reduction: out = relu(bias + sum_s partial) ----
__global__ void reduce_relu_kernel(const float* __restrict__ partial, const float* __restrict__ bias,
                                   float* __restrict__ out, int S, int M, int N, long sC) {
    int t = blockIdx.x*blockDim.x + threadIdx.x;
    int total = NI*M*N;
    if (t >= total) return;
    int nimg = t / (M*N);
    int mn   = t % (M*N);
    int m    = mn / N;
    float s = bias[m];
    for (int si = 0; si < S; si++)
        s += partial[((long)si*NI + nimg)*M*N + mn];
    out[(long)nimg*sC + mn] = fmaxf(s, 0.f);
}

// =================== 3x3 stride-2 maxpool SAME ===================
__global__ void maxpool3s2(const float* __restrict__ in, float* __restrict__ out,
                           int C, int Hin, int Hout) {
    int t = blockIdx.x*blockDim.x + threadIdx.x;
    int total = NI*C*Hout*Hout;
    if (t >= total) return;
    int ox = t % Hout;
    int oy = (t / Hout) % Hout;
    int nc = t / (Hout*Hout);
    const float* ip = in + (size_t)nc*Hin*Hin;
    float m = -INFINITY;
    #pragma unroll
    for (int ky = 0; ky < 3; ky++) {
        int iy = 2*oy + ky;
        if (iy >= Hin) continue;
        #pragma unroll
        for (int kx = 0; kx < 3; kx++) {
            int ix = 2*ox + kx;
            if (ix >= Hin) continue;
            m = fmaxf(m, ip[iy*Hin+ix]);
        }
    }
    out[t] = m;
}

__global__ void gap_kernel(const float* __restrict__ c5, float* __restrict__ glb) {
    int t = blockIdx.x*blockDim.x + threadIdx.x;
    if (t >= NI*528) return;
    const float* p = c5 + (size_t)t*100;
    float s = 0.f;
    for (int i = 0; i < 100; i++) s += p[i];
    glb[t] = s / 100.f;
}

__global__ void gfc_kernel(const float* __restrict__ glb, const float* __restrict__ wg,
                           const float* __restrict__ bg, float* __restrict__ gfc) {
    int t = blockIdx.x*blockDim.x + threadIdx.x;
    if (t >= NI*245) return;
    int k = t % 245, n = t / 245;
    float s = bg[k];
    const float* g = glb + n*528;
    for (int c = 0; c < 528; c++) s += g[c] * wg[c*245 + k];
    gfc[t] = s;
}

// ---- depthwise 5x5 SAME + relu ----
__global__ void dw5_kernel(const float* __restrict__ in, const float* __restrict__ w,
                           const float* __restrict__ bias, float* __restrict__ out) {
    int t = blockIdx.x*blockDim.x + threadIdx.x;
    int total = NI*245*400;
    if (t >= total) return;
    int p = t % 400;
    int k = (t / 400) % 245;
    int y = p / 20, x = p % 20;
    const float* ip = in + (size_t)(t/400)*400;
    const float* wk = w + k*25;
    float s = bias[k];
    #pragma unroll
    for (int ky = 0; ky < 5; ky++) {
        int iy = y - 2 + ky;
        if (iy < 0 || iy >= 20) continue;
        #pragma unroll
        for (int kx = 0; kx < 5; kx++) {
            int ix = x - 2 + kx;
            if (ix < 0 || ix >= 20) continue;
            s += ip[iy*20+ix] * wk[ky*5+kx];
        }
    }
    out[t] = fmaxf(s, 0.f);
}

// ---- scores + decoded boxes + sort keys ----
__global__ void scorebox_kernel(const float* __restrict__ clsmap, const float* __restrict__ regmap,
                                float* __restrict__ boxes, unsigned long long* __restrict__ keys) {
    int t = blockIdx.x*blockDim.x + threadIdx.x;
    if (t >= NI*NANCH) return;
    int i = t % NANCH;
    int n = t / NANCH;
    int a = i % 25;
    int x = (i / 25) % 20;
    int y = i / 500;
    int p = y*20 + x;
    const float* cm = clsmap + (size_t)n*50*400;
    float c0 = cm[(a*2  )*400 + p];
    float c1 = cm[(a*2+1)*400 + p];
    float score = 1.f / (1.f + expf(c0 - c1));
    const float* rm = regmap + (size_t)n*100*400;
    float d0 = rm[(a*4  )*400 + p];
    float d1 = rm[(a*4+1)*400 + p];
    float d2 = rm[(a*4+2)*400 + p];
    float d3 = rm[(a*4+3)*400 + p];
    const float scales[5] = {32.f, 64.f, 128.f, 256.f, 512.f};
    const float ratios[5] = {0.5f, 0.75f, 1.0f, 4.0f/3.0f, 2.0f};
    int si = a / 5, ri = a % 5;
    float sq = sqrtf(ratios[ri]);
    float aw = scales[si] / sq;
    float ah = scales[si] * sq;
    float acx = (x + 0.5f) * 16.f;
    float acy = (y + 0.5f) * 16.f;
    float cx = d0*aw + acx;
    float cy = d1*ah + acy;
    float w  = expf(d2) * aw;
    float h  = expf(d3) * ah;
    float* b = boxes + ((size_t)n*NANCH + i)*4;
    b[0] = fminf(fmaxf(cx - 0.5f*w, 0.f), 319.f);
    b[1] = fminf(fmaxf(cy - 0.5f*h, 0.f), 319.f);
    b[2] = fminf(fmaxf(cx + 0.5f*w, 0.f), 319.f);
    b[3] = fminf(fmaxf(cy + 0.5f*h, 0.f), 319.f);
    unsigned sb = __float_as_uint(score);  // score > 0 -> bit-monotone
    keys[t] = ((unsigned long long)sb << 32) | (unsigned long long)(0xFFFFFFFFu - (unsigned)i);
}

// ---- exact top-1000 per image: 64-bit radix select + bitonic sort of 1024 ----
__global__ void __launch_bounds__(1024)
topk_kernel(const unsigned long long* __restrict__ keys,
            const float* __restrict__ boxes, float* __restrict__ bk) {
    __shared__ unsigned int hist[256];
    __shared__ unsigned long long sh_prefix;
    __shared__ int sh_need;
    __shared__ unsigned int sh_cnt;
    __shared__ unsigned long long sk[1024];
    int n = blockIdx.x;
    int tid = threadIdx.x;
    const unsigned long long* kp = keys + (size_t)n*NANCH;

    if (tid == 0) { sh_prefix = 0ull; sh_need = PRENMS; sh_cnt = 0u; }
    __syncthreads();

    for (int shift = 56; shift >= 0; shift -= 8) {
        if (tid < 256) hist[tid] = 0u;
        __syncthreads();
        unsigned long long prefmask = (shift == 56) ? 0ull : (~0ull << (shift + 8));
        unsigned long long pref = sh_prefix;
        for (int i = tid; i < NANCH; i += 1024) {
            unsigned long long k = kp[i];
            if ((k & prefmask) == pref)
                atomicAdd(&hist[(unsigned)(k >> shift) & 255u], 1u);
        }
        __syncthreads();
        if (tid == 0) {
            int need = sh_need;
            unsigned cum = 0;
            int d = 255;
            for (; d >= 0; d--) { cum += hist[d]; if ((int)cum >= need) break; }
            sh_need = need - (int)(cum - hist[d]);
            sh_prefix = pref | ((unsigned long long)d << shift);
        }
        __syncthreads();
    }
    unsigned long long T = sh_prefix;

    if (tid < 24) sk[1000 + tid] = 0ull;
    for (int i = tid; i < NANCH; i += 1024) {
        unsigned long long k = kp[i];
        if (k >= T) sk[atomicAdd(&sh_cnt, 1u)] = k;
    }
    __syncthreads();

    for (int size = 2; size <= 1024; size <<= 1) {
        for (int stride = size >> 1; stride > 0; stride >>= 1) {
            if (tid < 512) {
                int lo = ((tid & ~(stride-1)) << 1) | (tid & (stride-1));
                int hi = lo + stride;
                unsigned long long a = sk[lo], c = sk[hi];
                bool desc = ((lo & size) == 0);
                if (desc ? (a < c) : (a > c)) { sk[lo] = c; sk[hi] = a; }
            }
            __syncthreads();
        }
    }

    if (tid < PRENMS) {
        unsigned idx = 0xFFFFFFFFu - (unsigned)(sk[tid] & 0xFFFFFFFFull);
        const float* src = boxes + ((size_t)n*NANCH + idx)*4;
        float* dst = bk + ((size_t)n*PRENMS + tid)*4;
        dst[0] = src[0]; dst[1] = src[1]; dst[2] = src[2]; dst[3] = src[3];
    }
}

// ---- suppression bitmask ----
__global__ void __launch_bounds__(256)
nms_mask_kernel(const float* __restrict__ bk, unsigned int* __restrict__ mask) {
    __shared__ float4 box[PRENMS];
    __shared__ float  area[PRENMS];
    int n = blockIdx.x;
    int i0 = blockIdx.y * 8;
    int tid = threadIdx.x;
    const float* b = bk + (size_t)n*PRENMS*4;
    for (int i = tid; i < PRENMS; i += 256) {
        float x1 = b[i*4], y1 = b[i*4+1], x2 = b[i*4+2], y2 = b[i*4+3];
        box[i] = make_float4(x1, y1, x2, y2);
        area[i] = (x2-x1)*(y2-y1);
    }
    __syncthreads();
    int w  = tid & 31;
    int il = tid >> 5;
    int i = i0 + il;
    if (i >= PRENMS) return;
    float4 bi = box[i];
    float ai = area[i];
    unsigned m = 0u;
    int jbase = w * 32;
    #pragma unroll 4
    for (int bbit = 0; bbit < 32; bbit++) {
        int j = jbase + bbit;
        if (j > i && j < PRENMS) {
            float ix1 = fmaxf(bi.x, box[j].x);
            float iy1 = fmaxf(bi.y, box[j].y);
            float ix2 = fminf(bi.z, box[j].z);
            float iy2 = fminf(bi.w, box[j].w);
            float inter = fmaxf(ix2-ix1, 0.f) * fmaxf(iy2-iy1, 0.f);
            float iou = inter / (ai + area[j] - inter + 1e-9f);
            if (iou > 0.7f) m |= (1u << bbit);
        }
    }
    mask[((size_t)n*1024 + i)*32 + w] = m;
}

// ---- single-warp NMS scan + stable partition -> 200 rois ----
__global__ void __launch_bounds__(32)
nms_scan_kernel(const unsigned int* __restrict__ mask, const float* __restrict__ bk,
                float* __restrict__ rois, float* __restrict__ out_rois) {
    __shared__ unsigned char keep[PRENMS];
    __shared__ int order[NROIS];
    int n = blockIdx.x;
    int lane = threadIdx.x;
    const unsigned int* mp = mask + (size_t)n*1024*32;
    unsigned removed = 0u;
    unsigned next_m = mp[0*32 + lane];
    for (int i = 0; i < PRENMS; i++) {
        unsigned m = next_m;
        if (i + 1 < PRENMS) next_m = mp[(i+1)*32 + lane];
        unsigned rw = __shfl_sync(0xFFFFFFFFu, removed, i >> 5);
        bool keep_i = ((rw >> (i & 31)) & 1u) == 0u;
        if (keep_i) removed |= m;
        if (lane == 0) keep[i] = keep_i ? 1 : 0;
    }
    __syncwarp();
    if (lane == 0) {
        int c = 0;
        for (int i = 0; i < PRENMS && c < NROIS; i++) if (keep[i])  order[c++] = i;
        for (int i = 0; i < PRENMS && c < NROIS; i++) if (!keep[i]) order[c++] = i;
    }
    __syncwarp();
    const float* b = bk + (size_t)n*PRENMS*4;
    for (int r = lane; r < NROIS; r += 32) {
        int idx = order[r];
        float x1 = b[idx*4], y1 = b[idx*4+1], x2 = b[idx*4+2], y2 = b[idx*4+3];
        float* dst = rois + ((size_t)n*NROIS + r)*4;
        dst[0] = x1; dst[1] = y1; dst[2] = x2; dst[3] = y2;
        float* o = out_rois + ((size_t)n*NROIS + r)*4;
        o[0] = x1; o[1] = y1; o[2] = x2; o[3] = y2;
    }
}

// ---- PSRoI pooling: stores TRANSPOSED froiT[c][n*200+r] for fc1 GEMM ----
__global__ void psroi_kernel(const float* __restrict__ fsam, const float* __restrict__ rois,
                             float* __restrict__ froiT) {
    int t = blockIdx.x*blockDim.x + threadIdx.x;
    int total = NI*NROIS*245;
    if (t >= total) return;
    int c = t % 245;
    int r = (t / 245) % NROIS;
    int n = t / (245*NROIS);
    const float* ro = rois + ((size_t)n*NROIS + r)*4;
    float x1 = ro[0] * (1.f/16.f), y1 = ro[1] * (1.f/16.f);
    float x2 = ro[2] * (1.f/16.f), y2 = ro[3] * (1.f/16.f);
    float bw = fmaxf(x2-x1, 0.1f) * (1.f/7.f);
    float bh = fmaxf(y2-y1, 0.1f) * (1.f/7.f);
    int ij = c % 49;
    int i = ij / 7, j = ij % 7;
    float sx = x1 + (j + 0.5f) * bw;
    float sy = y1 + (i + 0.5f) * bh;
    float x = fminf(fmaxf(sx, 0.f), 19.f);
    float y = fminf(fmaxf(sy, 0.f), 19.f);
    int y0 = min(max((int)floorf(y), 0), 18);
    int x0 = min(max((int)floorf(x), 0), 18);
    float wy = y - (float)y0;
    float wx = x - (float)x0;
    const float* f = fsam + ((size_t)n*245 + c)*400;
    float v00 = f[y0*20 + x0],     v01 = f[y0*20 + x0 + 1];
    float v10 = f[(y0+1)*20 + x0], v11 = f[(y0+1)*20 + x0 + 1];
    float v = v00*(1.f-wy)*(1.f-wx) + v01*(1.f-wy)*wx + v10*wy*(1.f-wx) + v11*wy*wx;
    froiT[(size_t)c*(NI*NROIS) + (size_t)n*NROIS + r] = v;
}

// ---- FC2 heads: one warp per (row, output) ----
__global__ void __launch_bounds__(256)
fc2_warp(const float* __restrict__ h, const float* __restrict__ cfw,
         const float* __restrict__ cfb, const float* __restrict__ rfw,
         const float* __restrict__ rfb, float* __restrict__ out_cls,
         float* __restrict__ out_reg) {
    int w = (blockIdx.x*blockDim.x + threadIdx.x) >> 5;
    int lane = threadIdx.x & 31;
    if (w >= NI*NROIS*25) return;
    int m = w % 25;
    int row = w / 25;
    const float* hr = h + (size_t)row*1024;
    float s = 0.f;
    if (m < 21) {
        for (int k = lane; k < 1024; k += 32) s = fmaf(hr[k], cfw[k*21 + m], s);
    } else {
        int mm = m - 21;
        for (int k = lane; k < 1024; k += 32) s = fmaf(hr[k], rfw[k*4 + mm], s);
    }
    #pragma unroll
    for (int o = 16; o > 0; o >>= 1) s += __shfl_down_sync(0xFFFFFFFFu, s, o);
    if (lane == 0) {
        if (m < 21) out_cls[row*21 + m] = s + cfb[m];
        else        out_reg[row*4 + (m-21)] = s + rfb[m-21];
    }
}

extern "C" void kernel_launch(void* const* d_in, const int* in_sizes, int n_in,
                              void* d_out, int out_size) {
    const float* x      = (const float*)d_in[0];
    const float* w1     = (const float*)d_in[1];
    const float* b1     = (const float*)d_in[2];
    const float* w2     = (const float*)d_in[3];
    const float* b2     = (const float*)d_in[4];
    const float* w3     = (const float*)d_in[5];
    const float* b3     = (const float*)d_in[6];
    const float* w4     = (const float*)d_in[7];
    const float* b4     = (const float*)d_in[8];
    const float* cem_w4 = (const float*)d_in[9];
    const float* cem_b4 = (const float*)d_in[10];
    const float* cem_w5 = (const float*)d_in[11];
    const float* cem_b5 = (const float*)d_in[12];
    const float* cem_wg = (const float*)d_in[13];
    const float* cem_bg = (const float*)d_in[14];
    const float* rpn_dw = (const float*)d_in[15];
    const float* rpn_dwb= (const float*)d_in[16];
    const float* rpn_pw = (const float*)d_in[17];
    const float* rpn_pwb= (const float*)d_in[18];
    const float* cls_w  = (const float*)d_in[19];
    const float* cls_b  = (const float*)d_in[20];
    const float* reg_w  = (const float*)d_in[21];
    const float* reg_b  = (const float*)d_in[22];
    const float* sam_w  = (const float*)d_in[23];
    const float* sam_b  = (const float*)d_in[24];
    const float* fc_w   = (const float*)d_in[25];
    const float* fc_b   = (const float*)d_in[26];
    const float* cls_fw = (const float*)d_in[27];
    const float* cls_fb = (const float*)d_in[28];
    const float* reg_fw = (const float*)d_in[29];
    const float* reg_fb = (const float*)d_in[30];
    float* out = (float*)d_out;

    float* buf = nullptr;
    cudaGetSymbolAddress((void**)&buf, g_buf);
    unsigned long long* keys = nullptr;
    cudaGetSymbolAddress((void**)&keys, g_keys);
    unsigned int* mask = nullptr;
    cudaGetSymbolAddress((void**)&mask, g_mask);

    const int TB = 256;
    float* part = buf + O_PART;

    // ---- conv1: 3->24, 320->160 (implicit GEMM, small tile: M=24) ----
    gemm_tiled<1,true><<<dim3(CDIV(25600,64), 1, NI), 256>>>(
        w1, x, b1, buf+O_C1, 24, 27, 25600, (long)3*320*320, (long)24*25600,
        nullptr, nullptr, 3, 320, 160);
    maxpool3s2<<<CDIV(NI*24*80*80, TB), TB>>>(buf+O_C1, buf+O_P1, 24, 160, 80);
    // ---- conv2: 24->132, 80->40 (implicit GEMM, fat threads) ----
    gemm_fat<1,false,true><<<dim3(CDIV(1600,64), CDIV(132,64), NI), 128>>>(
        w2, buf+O_P1, b2, buf+O_C3, 132, 216, 1600, (long)24*80*80, (long)132*1600,
        24, 80, 40, 1, 216);
    // ---- conv3: 132->264, 40->20 (implicit GEMM, fat threads, split-K=4) ----
    gemm_fat<5,false,true><<<dim3(CDIV(400,64), CDIV(264,64), NI*4), 128>>>(
        w3, buf+O_C3, nullptr, part, 264, 1188, 400, (long)132*40*40, 0,
        132, 40, 20, 4, 297);
    reduce_relu_kernel<<<CDIV(NI*264*400, TB), TB>>>(part, b3, buf+O_C4, 4, 264, 400, (long)264*400);
    // ---- conv4: 264->528, 20->10 (implicit GEMM, fat threads, split-K=4) ----
    gemm_fat<5,false,true><<<dim3(CDIV(100,64), CDIV(528,64), NI*4), 128>>>(
        w4, buf+O_C4, nullptr, part, 528, 2376, 100, (long)264*20*20, 0,
        264, 20, 10, 4, 594);
    reduce_relu_kernel<<<CDIV(NI*528*100, TB), TB>>>(part, b4, buf+O_C5, 4, 528, 100, (long)528*100);

    // ---- CEM ----
    gap_kernel<<<CDIV(NI*528, TB), TB>>>(buf+O_C5, buf+O_GLB);
    gfc_kernel<<<CDIV(NI*245, TB), TB>>>(buf+O_GLB, cem_wg, cem_bg, buf+O_GFC);
    gemm_tiled<0,false><<<dim3(CDIV(100,64), CDIV(245,64), NI), 256>>>(
        cem_w5, buf+O_C5, cem_b5, buf+O_CEM5, 245, 528, 100,
        (long)528*100, (long)245*100, nullptr, nullptr, 0, 0, 0);
    gemm_tiled<3,false><<<dim3(CDIV(400,64), CDIV(245,64), NI), 256>>>(
        cem_w4, buf+O_C4, cem_b4, buf+O_FCEM, 245, 264, 400,
        (long)264*400, (long)245*400, buf+O_GFC, buf+O_CEM5, 0, 0, 0);

    // ---- RPN ----
    dw5_kernel<<<CDIV(NI*245*400, TB), TB>>>(buf+O_FCEM, rpn_dw, rpn_dwb, buf+O_T);
    gemm_tiled<1,false><<<dim3(CDIV(400,64), CDIV(256,64), NI), 256>>>(
        rpn_pw, buf+O_T, rpn_pwb, buf+O_FRPN, 256, 245, 400,
        (long)245*400, (long)256*400, nullptr, nullptr, 0, 0, 0);
    gemm_tiled<0,false><<<dim3(CDIV(400,64), CDIV(50,64), NI), 256>>>(
        cls_w, buf+O_FRPN, cls_b, buf+O_CLS, 50, 256, 400,
        (long)256*400, (long)50*400, nullptr, nullptr, 0, 0, 0);
    gemm_tiled<0,false><<<dim3(CDIV(400,64), CDIV(100,64), NI), 256>>>(
        reg_w, buf+O_FRPN, reg_b, buf+O_REG, 100, 256, 400,
        (long)256*400, (long)100*400, nullptr, nullptr, 0, 0, 0);
    gemm_tiled<2,false><<<dim3(CDIV(400,64), CDIV(245,64), NI), 256>>>(
        sam_w, buf+O_FRPN, sam_b, buf+O_FSAM, 245, 256, 400,
        (long)256*400, (long)245*400, buf+O_FCEM, nullptr, 0, 0, 0);

    // ---- proposals ----
    scorebox_kernel<<<CDIV(NI*NANCH, TB), TB>>>(buf+O_CLS, buf+O_REG, buf+O_BOX, keys);
    topk_kernel<<<NI, 1024>>>(keys, buf+O_BOX, buf+O_BK);
    nms_mask_kernel<<<dim3(NI, 125), 256>>>(buf+O_BK, mask);
    nms_scan_kernel<<<NI, 32>>>(mask, buf+O_BK, buf+O_ROI,
                                out + (size_t)NI*NROIS*21 + (size_t)NI*NROIS*4);

    // ---- head ----
    psroi_kernel<<<CDIV(NI*NROIS*245, TB), TB>>>(buf+O_FSAM, buf+O_ROI, buf+O_FROI);
    gemm_fat<4,true,false><<<dim3(CDIV(NI*NROIS,64), CDIV(1024,64), 1), 128>>>(
        fc_w, buf+O_FROI, fc_b, buf+O_H, 1024, 245, NI*NROIS, 0, 0,
        0, 0, 0, 1, 245);
    fc2_warp<<<CDIV(NI*NROIS*25*32, TB), TB>>>(buf+O_H, cls_fw, cls_fb, reg_fw, reg_fb,
                                               out, out + (size_t)NI*NROIS*21);
}

// round 11
// speedup vs baseline: 1.1789x; 1.1450x over previous
#include <cuda_runtime.h>
#include <math.h>

#define CDIV(a,b) (((a)+(b)-1)/(b))

constexpr int NI     = 8;
constexpr int NANCH  = 10000;
constexpr int PRENMS = 1000;
constexpr int NROIS  = 200;
constexpr int SPLITK = 8;

// ---- scratch layout (floats) ----
constexpr size_t O_C1  = 0;                constexpr size_t S_C1  = (size_t)NI*24*160*160;
constexpr size_t O_P1  = O_C1 + S_C1;      constexpr size_t S_P1  = (size_t)NI*24*80*80;
constexpr size_t O_C3  = O_P1 + S_P1;      constexpr size_t S_C3  = (size_t)NI*132*40*40;
constexpr size_t O_C4  = O_C3 + S_C3;      constexpr size_t S_C4  = (size_t)NI*264*20*20;
constexpr size_t O_C5  = O_C4 + S_C4;      constexpr size_t S_C5  = (size_t)NI*528*10*10;
constexpr size_t O_GLB = O_C5 + S_C5;      constexpr size_t S_GLB = (size_t)NI*528;
constexpr size_t O_GFC = O_GLB + S_GLB;    constexpr size_t S_GFC = (size_t)NI*245;
constexpr size_t O_CEM5= O_GFC + S_GFC;    constexpr size_t S_CEM5= (size_t)NI*245*100;
constexpr size_t O_FCEM= O_CEM5 + S_CEM5;  constexpr size_t S_FCEM= (size_t)NI*245*400;
constexpr size_t O_T   = O_FCEM + S_FCEM;  constexpr size_t S_T   = S_FCEM;
constexpr size_t O_FRPN= O_T + S_T;        constexpr size_t S_FRPN= (size_t)NI*256*400;
constexpr size_t O_CLS = O_FRPN + S_FRPN;  constexpr size_t S_CLS = (size_t)NI*50*400;
constexpr size_t O_REG = O_CLS + S_CLS;    constexpr size_t S_REG = (size_t)NI*100*400;
constexpr size_t O_FSAM= O_REG + S_REG;    constexpr size_t S_FSAM= S_FCEM;
constexpr size_t O_BOX = O_FSAM + S_FSAM;  constexpr size_t S_BOX = (size_t)NI*NANCH*4;
constexpr size_t O_BK  = O_BOX + S_BOX;    constexpr size_t S_BK  = (size_t)NI*PRENMS*4;
constexpr size_t O_ROI = O_BK + S_BK;      constexpr size_t S_ROI = (size_t)NI*NROIS*4;
constexpr size_t O_FROI= O_ROI + S_ROI;    constexpr size_t S_FROI= (size_t)245*NI*NROIS; // transposed [245][1600]
constexpr size_t O_H   = O_FROI + S_FROI;  constexpr size_t S_H   = (size_t)NI*NROIS*1024;
constexpr size_t O_PART= O_H + S_H;        constexpr size_t S_PART= (size_t)SPLITK*NI*264*400; // split-K partials (max: conv3)
constexpr size_t TOTAL = O_PART + S_PART;

__device__ float g_buf[TOTAL];
__device__ unsigned long long g_keys[(size_t)NI*NANCH];
__device__ unsigned int g_mask[(size_t)NI*1024*32];   // suppression bitmask [n][i][jword]

// =================== unified tiled GEMM with register-staged prefetch ===================
// 64x64 tile, 256 threads, 4x4/thread. C[m][n] = sum_k A[m][k]*B[k][n].
// MODE: 0 bias, 1 bias+relu, 2 fsam e1*sigmoid(s), 3 fcem adds,
//       4 relu + transposed store C[n][m], 5 raw partial store (split-K)
// CONV: B[k][n] is im2col of 3x3 stride-2 SAME conv input (decoded at load time)
template<int MODE, bool TRANSA, bool CONV>
__global__ void __launch_bounds__(256)
gemm_tiled(const float* __restrict__ A, const float* __restrict__ B,
           const float* __restrict__ bias, float* __restrict__ C,
           int M, int K, int N, long sB, long sC,
           const float* __restrict__ e1, const float* __restrict__ e2,
           int Cin, int Hin, int Hout, int S, int kLen) {
    __shared__ float As[16][68];
    __shared__ float Bs[16][68];
    int nimg, spl;
    if (MODE == 5) { nimg = blockIdx.z / S; spl = blockIdx.z % S; }
    else           { nimg = blockIdx.z;     spl = 0; }
    int kStart = spl * kLen;
    int kEnd   = min(K, kStart + kLen);
    int m0 = blockIdx.y*64, n0 = blockIdx.x*64;
    const float* Bp = B + (long)nimg*sB;
    float* Cp = (MODE == 5) ? C + ((long)spl*NI + nimg)*M*N
                            : C + (long)nimg*sC;
    int tid = threadIdx.x;
    int tx = tid % 16, ty = tid / 16;

    float pa[4], pb[4];

    auto fetchA = [&](int kf) {
        if (!TRANSA) {
            int r = tid >> 2, c = (tid & 3) * 4;
            #pragma unroll
            for (int i = 0; i < 4; i++) {
                int mm = m0 + r, kk = kf + c + i;
                pa[i] = (mm < M && kk < kEnd) ? A[(long)mm*K + kk] : 0.f;
            }
        } else {
            int r = tid >> 4, c = (tid & 15) * 4;
            #pragma unroll
            for (int i = 0; i < 4; i++) {
                int kk = kf + r, mm = m0 + c + i;
                pa[i] = (mm < M && kk < kEnd) ? A[(long)kk*M + mm] : 0.f;
            }
        }
    };
    auto storeA = [&]() {
        if (!TRANSA) {
            int r = tid >> 2, c = (tid & 3) * 4;
            #pragma unroll
            for (int i = 0; i < 4; i++) As[c+i][r] = pa[i];
        } else {
            int r = tid >> 4, c = (tid & 15) * 4;
            #pragma unroll
            for (int i = 0; i < 4; i++) As[r][c+i] = pa[i];
        }
    };
    auto fetchB = [&](int kf) {
        int r = tid >> 4, c = (tid & 15) * 4;
        if (CONV) {
            int kk = kf + r;
            bool kv = kk < kEnd;
            int ic = 0, ky = 0, kx = 0;
            if (kv) { ic = kk / 9; int rem = kk - ic*9; ky = rem / 3; kx = rem - ky*3; }
            #pragma unroll
            for (int i = 0; i < 4; i++) {
                int nn = n0 + c + i;
                float v = 0.f;
                if (kv && nn < N) {
                    int oy = nn / Hout, ox = nn - oy*Hout;
                    int iy = 2*oy + ky, ix = 2*ox + kx;
                    if (iy < Hin && ix < Hin)
                        v = Bp[((long)ic*Hin + iy)*Hin + ix];
                }
                pb[i] = v;
            }
        } else {
            int kk = kf + r;
            #pragma unroll
            for (int i = 0; i < 4; i++) {
                int nn = n0 + c + i;
                pb[i] = (kk < kEnd && nn < N) ? Bp[(long)kk*N + nn] : 0.f;
            }
        }
    };
    auto storeB = [&]() {
        int r = tid >> 4, c = (tid & 15) * 4;
        #pragma unroll
        for (int i = 0; i < 4; i++) Bs[r][c+i] = pb[i];
    };

    float acc[4][4] = {};
    fetchA(kStart);
    fetchB(kStart);
    for (int k0 = kStart; k0 < kEnd; k0 += 16) {
        storeA();
        storeB();
        __syncthreads();
        bool has_next = (k0 + 16 < kEnd);
        if (has_next) { fetchA(k0 + 16); fetchB(k0 + 16); }  // LDGs overlap FMAs below
        #pragma unroll
        for (int kk = 0; kk < 16; kk++) {
            float4 av = *reinterpret_cast<const float4*>(&As[kk][ty*4]);
            float4 bv = *reinterpret_cast<const float4*>(&Bs[kk][tx*4]);
            float a[4] = {av.x, av.y, av.z, av.w};
            float b[4] = {bv.x, bv.y, bv.z, bv.w};
            #pragma unroll
            for (int i = 0; i < 4; i++)
                #pragma unroll
                for (int j = 0; j < 4; j++)
                    acc[i][j] = fmaf(a[i], b[j], acc[i][j]);
        }
        __syncthreads();
    }
    #pragma unroll
    for (int i = 0; i < 4; i++) {
        int m = m0 + ty*4 + i;
        if (m >= M) continue;
        float bv = (MODE == 5) ? 0.f : bias[m];
        #pragma unroll
        for (int j = 0; j < 4; j++) {
            int n = n0 + tx*4 + j;
            if (n >= N) continue;
            float s = acc[i][j] + bv;
            if (MODE == 1) s = fmaxf(s, 0.f);
            else if (MODE == 2) {
                s = e1[(long)nimg*sC + (long)m*N + n] * (1.f/(1.f + expf(-s)));
            } else if (MODE == 3) {
                int y = n / 20, x = n % 20;
                s += e1[nimg*245 + m] + e2[((long)nimg*245 + m)*100 + (y/2)*10 + (x/2)];
            }
            if (MODE == 4) {
                s = fmaxf(s, 0.f);
                Cp[(long)n*M + m] = s;
            } else {
                Cp[(long)m*N + n] = s;
            }
        }
    }
}

// ---- split-K reduction: out = relu(bias + sum_s partial) ----
__global__ void reduce_relu_kernel(const float* __restrict__ partial, const float* __restrict__ bias,
                                   float* __restrict__ out, int S, int M, int N, long sC) {
    int t = blockIdx.x*blockDim.x + threadIdx.x;
    int total = NI*M*N;
    if (t >= total) return;
    int nimg = t / (M*N);
    int mn   = t % (M*N);
    int m    = mn / N;
    float s = bias[m];
    for (int si = 0; si < S; si++)
        s += partial[((long)si*NI + nimg)*M*N + mn];
    out[(long)nimg*sC + mn] = fmaxf(s, 0.f);
}

// =================== 3x3 stride-2 maxpool SAME ===================
__global__ void maxpool3s2(const float* __restrict__ in, float* __restrict__ out,
                           int C, int Hin, int Hout) {
    int t = blockIdx.x*blockDim.x + threadIdx.x;
    int total = NI*C*Hout*Hout;
    if (t >= total) return;
    int ox = t % Hout;
    int oy = (t / Hout) % Hout;
    int nc = t / (Hout*Hout);
    const float* ip = in + (size_t)nc*Hin*Hin;
    float m = -INFINITY;
    #pragma unroll
    for (int ky = 0; ky < 3; ky++) {
        int iy = 2*oy + ky;
        if (iy >= Hin) continue;
        #pragma unroll
        for (int kx = 0; kx < 3; kx++) {
            int ix = 2*ox + kx;
            if (ix >= Hin) continue;
            m = fmaxf(m, ip[iy*Hin+ix]);
        }
    }
    out[t] = m;
}

__global__ void gap_kernel(const float* __restrict__ c5, float* __restrict__ glb) {
    int t = blockIdx.x*blockDim.x + threadIdx.x;
    if (t >= NI*528) return;
    const float* p = c5 + (size_t)t*100;
    float s = 0.f;
    for (int i = 0; i < 100; i++) s += p[i];
    glb[t] = s / 100.f;
}

__global__ void gfc_kernel(const float* __restrict__ glb, const float* __restrict__ wg,
                           const float* __restrict__ bg, float* __restrict__ gfc) {
    int t = blockIdx.x*blockDim.x + threadIdx.x;
    if (t >= NI*245) return;
    int k = t % 245, n = t / 245;
    float s = bg[k];
    const float* g = glb + n*528;
    for (int c = 0; c < 528; c++) s += g[c] * wg[c*245 + k];
    gfc[t] = s;
}

// ---- depthwise 5x5 SAME + relu ----
__global__ void dw5_kernel(const float* __restrict__ in, const float* __restrict__ w,
                           const float* __restrict__ bias, float* __restrict__ out) {
    int t = blockIdx.x*blockDim.x + threadIdx.x;
    int total = NI*245*400;
    if (t >= total) return;
    int p = t % 400;
    int k = (t / 400) % 245;
    int y = p / 20, x = p % 20;
    const float* ip = in + (size_t)(t/400)*400;
    const float* wk = w + k*25;
    float s = bias[k];
    #pragma unroll
    for (int ky = 0; ky < 5; ky++) {
        int iy = y - 2 + ky;
        if (iy < 0 || iy >= 20) continue;
        #pragma unroll
        for (int kx = 0; kx < 5; kx++) {
            int ix = x - 2 + kx;
            if (ix < 0 || ix >= 20) continue;
            s += ip[iy*20+ix] * wk[ky*5+kx];
        }
    }
    out[t] = fmaxf(s, 0.f);
}

// ---- scores + decoded boxes + sort keys ----
__global__ void scorebox_kernel(const float* __restrict__ clsmap, const float* __restrict__ regmap,
                                float* __restrict__ boxes, unsigned long long* __restrict__ keys) {
    int t = blockIdx.x*blockDim.x + threadIdx.x;
    if (t >= NI*NANCH) return;
    int i = t % NANCH;
    int n = t / NANCH;
    int a = i % 25;
    int x = (i / 25) % 20;
    int y = i / 500;
    int p = y*20 + x;
    const float* cm = clsmap + (size_t)n*50*400;
    float c0 = cm[(a*2  )*400 + p];
    float c1 = cm[(a*2+1)*400 + p];
    float score = 1.f / (1.f + expf(c0 - c1));
    const float* rm = regmap + (size_t)n*100*400;
    float d0 = rm[(a*4  )*400 + p];
    float d1 = rm[(a*4+1)*400 + p];
    float d2 = rm[(a*4+2)*400 + p];
    float d3 = rm[(a*4+3)*400 + p];
    const float scales[5] = {32.f, 64.f, 128.f, 256.f, 512.f};
    const float ratios[5] = {0.5f, 0.75f, 1.0f, 4.0f/3.0f, 2.0f};
    int si = a / 5, ri = a % 5;
    float sq = sqrtf(ratios[ri]);
    float aw = scales[si] / sq;
    float ah = scales[si] * sq;
    float acx = (x + 0.5f) * 16.f;
    float acy = (y + 0.5f) * 16.f;
    float cx = d0*aw + acx;
    float cy = d1*ah + acy;
    float w  = expf(d2) * aw;
    float h  = expf(d3) * ah;
    float* b = boxes + ((size_t)n*NANCH + i)*4;
    b[0] = fminf(fmaxf(cx - 0.5f*w, 0.f), 319.f);
    b[1] = fminf(fmaxf(cy - 0.5f*h, 0.f), 319.f);
    b[2] = fminf(fmaxf(cx + 0.5f*w, 0.f), 319.f);
    b[3] = fminf(fmaxf(cy + 0.5f*h, 0.f), 319.f);
    unsigned sb = __float_as_uint(score);  // score > 0 -> bit-monotone
    keys[t] = ((unsigned long long)sb << 32) | (unsigned long long)(0xFFFFFFFFu - (unsigned)i);
}

// ---- exact top-1000 per image: 64-bit radix select + bitonic sort of 1024 ----
__global__ void __launch_bounds__(1024)
topk_kernel(const unsigned long long* __restrict__ keys,
            const float* __restrict__ boxes, float* __restrict__ bk) {
    __shared__ unsigned int hist[256];
    __shared__ unsigned long long sh_prefix;
    __shared__ int sh_need;
    __shared__ unsigned int sh_cnt;
    __shared__ unsigned long long sk[1024];
    int n = blockIdx.x;
    int tid = threadIdx.x;
    const unsigned long long* kp = keys + (size_t)n*NANCH;

    if (tid == 0) { sh_prefix = 0ull; sh_need = PRENMS; sh_cnt = 0u; }
    __syncthreads();

    for (int shift = 56; shift >= 0; shift -= 8) {
        if (tid < 256) hist[tid] = 0u;
        __syncthreads();
        unsigned long long prefmask = (shift == 56) ? 0ull : (~0ull << (shift + 8));
        unsigned long long pref = sh_prefix;
        for (int i = tid; i < NANCH; i += 1024) {
            unsigned long long k = kp[i];
            if ((k & prefmask) == pref)
                atomicAdd(&hist[(unsigned)(k >> shift) & 255u], 1u);
        }
        __syncthreads();
        if (tid == 0) {
            int need = sh_need;
            unsigned cum = 0;
            int d = 255;
            for (; d >= 0; d--) { cum += hist[d]; if ((int)cum >= need) break; }
            sh_need = need - (int)(cum - hist[d]);
            sh_prefix = pref | ((unsigned long long)d << shift);
        }
        __syncthreads();
    }
    unsigned long long T = sh_prefix;

    if (tid < 24) sk[1000 + tid] = 0ull;
    for (int i = tid; i < NANCH; i += 1024) {
        unsigned long long k = kp[i];
        if (k >= T) sk[atomicAdd(&sh_cnt, 1u)] = k;
    }
    __syncthreads();

    for (int size = 2; size <= 1024; size <<= 1) {
        for (int stride = size >> 1; stride > 0; stride >>= 1) {
            if (tid < 512) {
                int lo = ((tid & ~(stride-1)) << 1) | (tid & (stride-1));
                int hi = lo + stride;
                unsigned long long a = sk[lo], c = sk[hi];
                bool desc = ((lo & size) == 0);
                if (desc ? (a < c) : (a > c)) { sk[lo] = c; sk[hi] = a; }
            }
            __syncthreads();
        }
    }

    if (tid < PRENMS) {
        unsigned idx = 0xFFFFFFFFu - (unsigned)(sk[tid] & 0xFFFFFFFFull);
        const float* src = boxes + ((size_t)n*NANCH + idx)*4;
        float* dst = bk + ((size_t)n*PRENMS + tid)*4;
        dst[0] = src[0]; dst[1] = src[1]; dst[2] = src[2]; dst[3] = src[3];
    }
}

// ---- suppression bitmask ----
__global__ void __launch_bounds__(256)
nms_mask_kernel(const float* __restrict__ bk, unsigned int* __restrict__ mask) {
    __shared__ float4 box[PRENMS];
    __shared__ float  area[PRENMS];
    int n = blockIdx.x;
    int i0 = blockIdx.y * 8;
    int tid = threadIdx.x;
    const float* b = bk + (size_t)n*PRENMS*4;
    for (int i = tid; i < PRENMS; i += 256) {
        float x1 = b[i*4], y1 = b[i*4+1], x2 = b[i*4+2], y2 = b[i*4+3];
        box[i] = make_float4(x1, y1, x2, y2);
        area[i] = (x2-x1)*(y2-y1);
    }
    __syncthreads();
    int w  = tid & 31;
    int il = tid >> 5;
    int i = i0 + il;
    if (i >= PRENMS) return;
    float4 bi = box[i];
    float ai = area[i];
    unsigned m = 0u;
    int jbase = w * 32;
    #pragma unroll 4
    for (int bbit = 0; bbit < 32; bbit++) {
        int j = jbase + bbit;
        if (j > i && j < PRENMS) {
            float ix1 = fmaxf(bi.x, box[j].x);
            float iy1 = fmaxf(bi.y, box[j].y);
            float ix2 = fminf(bi.z, box[j].z);
            float iy2 = fminf(bi.w, box[j].w);
            float inter = fmaxf(ix2-ix1, 0.f) * fmaxf(iy2-iy1, 0.f);
            float iou = inter / (ai + area[j] - inter + 1e-9f);
            if (iou > 0.7f) m |= (1u << bbit);
        }
    }
    mask[((size_t)n*1024 + i)*32 + w] = m;
}

// ---- single-warp NMS scan + stable partition -> 200 rois ----
__global__ void __launch_bounds__(32)
nms_scan_kernel(const unsigned int* __restrict__ mask, const float* __restrict__ bk,
                float* __restrict__ rois, float* __restrict__ out_rois) {
    __shared__ unsigned char keep[PRENMS];
    __shared__ int order[NROIS];
    int n = blockIdx.x;
    int lane = threadIdx.x;
    const unsigned int* mp = mask + (size_t)n*1024*32;
    unsigned removed = 0u;
    unsigned next_m = mp[0*32 + lane];
    for (int i = 0; i < PRENMS; i++) {
        unsigned m = next_m;
        if (i + 1 < PRENMS) next_m = mp[(i+1)*32 + lane];
        unsigned rw = __shfl_sync(0xFFFFFFFFu, removed, i >> 5);
        bool keep_i = ((rw >> (i & 31)) & 1u) == 0u;
        if (keep_i) removed |= m;
        if (lane == 0) keep[i] = keep_i ? 1 : 0;
    }
    __syncwarp();
    if (lane == 0) {
        int c = 0;
        for (int i = 0; i < PRENMS && c < NROIS; i++) if (keep[i])  order[c++] = i;
        for (int i = 0; i < PRENMS && c < NROIS; i++) if (!keep[i]) order[c++] = i;
    }
    __syncwarp();
    const float* b = bk + (size_t)n*PRENMS*4;
    for (int r = lane; r < NROIS; r += 32) {
        int idx = order[r];
        float x1 = b[idx*4], y1 = b[idx*4+1], x2 = b[idx*4+2], y2 = b[idx*4+3];
        float* dst = rois + ((size_t)n*NROIS + r)*4;
        dst[0] = x1; dst[1] = y1; dst[2] = x2; dst[3] = y2;
        float* o = out_rois + ((size_t)n*NROIS + r)*4;
        o[0] = x1; o[1] = y1; o[2] = x2; o[3] = y2;
    }
}

// ---- PSRoI pooling: stores TRANSPOSED froiT[c][n*200+r] for fc1 GEMM ----
__global__ void psroi_kernel(const float* __restrict__ fsam, const float* __restrict__ rois,
                             float* __restrict__ froiT) {
    int t = blockIdx.x*blockDim.x + threadIdx.x;
    int total = NI*NROIS*245;
    if (t >= total) return;
    int c = t % 245;
    int r = (t / 245) % NROIS;
    int n = t / (245*NROIS);
    const float* ro = rois + ((size_t)n*NROIS + r)*4;
    float x1 = ro[0] * (1.f/16.f), y1 = ro[1] * (1.f/16.f);
    float x2 = ro[2] * (1.f/16.f), y2 = ro[3] * (1.f/16.f);
    float bw = fmaxf(x2-x1, 0.1f) * (1.f/7.f);
    float bh = fmaxf(y2-y1, 0.1f) * (1.f/7.f);
    int ij = c % 49;
    int i = ij / 7, j = ij % 7;
    float sx = x1 + (j + 0.5f) * bw;
    float sy = y1 + (i + 0.5f) * bh;
    float x = fminf(fmaxf(sx, 0.f), 19.f);
    float y = fminf(fmaxf(sy, 0.f), 19.f);
    int y0 = min(max((int)floorf(y), 0), 18);
    int x0 = min(max((int)floorf(x), 0), 18);
    float wy = y - (float)y0;
    float wx = x - (float)x0;
    const float* f = fsam + ((size_t)n*245 + c)*400;
    float v00 = f[y0*20 + x0],     v01 = f[y0*20 + x0 + 1];
    float v10 = f[(y0+1)*20 + x0], v11 = f[(y0+1)*20 + x0 + 1];
    float v = v00*(1.f-wy)*(1.f-wx) + v01*(1.f-wy)*wx + v10*wy*(1.f-wx) + v11*wy*wx;
    froiT[(size_t)c*(NI*NROIS) + (size_t)n*NROIS + r] = v;
}

// ---- FC2 heads: one warp per (row, output) ----
__global__ void __launch_bounds__(256)
fc2_warp(const float* __restrict__ h, const float* __restrict__ cfw,
         const float* __restrict__ cfb, const float* __restrict__ rfw,
         const float* __restrict__ rfb, float* __restrict__ out_cls,
         float* __restrict__ out_reg) {
    int w = (blockIdx.x*blockDim.x + threadIdx.x) >> 5;
    int lane = threadIdx.x & 31;
    if (w >= NI*NROIS*25) return;
    int m = w % 25;
    int row = w / 25;
    const float* hr = h + (size_t)row*1024;
    float s = 0.f;
    if (m < 21) {
        for (int k = lane; k < 1024; k += 32) s = fmaf(hr[k], cfw[k*21 + m], s);
    } else {
        int mm = m - 21;
        for (int k = lane; k < 1024; k += 32) s = fmaf(hr[k], rfw[k*4 + mm], s);
    }
    #pragma unroll
    for (int o = 16; o > 0; o >>= 1) s += __shfl_down_sync(0xFFFFFFFFu, s, o);
    if (lane == 0) {
        if (m < 21) out_cls[row*21 + m] = s + cfb[m];
        else        out_reg[row*4 + (m-21)] = s + rfb[m-21];
    }
}

extern "C" void kernel_launch(void* const* d_in, const int* in_sizes, int n_in,
                              void* d_out, int out_size) {
    const float* x      = (const float*)d_in[0];
    const float* w1     = (const float*)d_in[1];
    const float* b1     = (const float*)d_in[2];
    const float* w2     = (const float*)d_in[3];
    const float* b2     = (const float*)d_in[4];
    const float* w3     = (const float*)d_in[5];
    const float* b3     = (const float*)d_in[6];
    const float* w4     = (const float*)d_in[7];
    const float* b4     = (const float*)d_in[8];
    const float* cem_w4 = (const float*)d_in[9];
    const float* cem_b4 = (const float*)d_in[10];
    const float* cem_w5 = (const float*)d_in[11];
    const float* cem_b5 = (const float*)d_in[12];
    const float* cem_wg = (const float*)d_in[13];
    const float* cem_bg = (const float*)d_in[14];
    const float* rpn_dw = (const float*)d_in[15];
    const float* rpn_dwb= (const float*)d_in[16];
    const float* rpn_pw = (const float*)d_in[17];
    const float* rpn_pwb= (const float*)d_in[18];
    const float* cls_w  = (const float*)d_in[19];
    const float* cls_b  = (const float*)d_in[20];
    const float* reg_w  = (const float*)d_in[21];
    const float* reg_b  = (const float*)d_in[22];
    const float* sam_w  = (const float*)d_in[23];
    const float* sam_b  = (const float*)d_in[24];
    const float* fc_w   = (const float*)d_in[25];
    const float* fc_b   = (const float*)d_in[26];
    const float* cls_fw = (const float*)d_in[27];
    const float* cls_fb = (const float*)d_in[28];
    const float* reg_fw = (const float*)d_in[29];
    const float* reg_fb = (const float*)d_in[30];
    float* out = (float*)d_out;

    float* buf = nullptr;
    cudaGetSymbolAddress((void**)&buf, g_buf);
    unsigned long long* keys = nullptr;
    cudaGetSymbolAddress((void**)&keys, g_keys);
    unsigned int* mask = nullptr;
    cudaGetSymbolAddress((void**)&mask, g_mask);

    const int TB = 256;
    float* part = buf + O_PART;

    // ---- conv1: 3->24, 320->160 (implicit GEMM) ----
    gemm_tiled<1,false,true><<<dim3(CDIV(25600,64), 1, NI), 256>>>(
        w1, x, b1, buf+O_C1, 24, 27, 25600, (long)3*320*320, (long)24*25600,
        nullptr, nullptr, 3, 320, 160, 1, 27);
    maxpool3s2<<<CDIV(NI*24*80*80, TB), TB>>>(buf+O_C1, buf+O_P1, 24, 160, 80);
    // ---- conv2: 24->132, 80->40 (implicit GEMM) ----
    gemm_tiled<1,false,true><<<dim3(CDIV(1600,64), CDIV(132,64), NI), 256>>>(
        w2, buf+O_P1, b2, buf+O_C3, 132, 216, 1600, (long)24*80*80, (long)132*1600,
        nullptr, nullptr, 24, 80, 40, 1, 216);
    // ---- conv3: 132->264, 40->20 (implicit GEMM, split-K=8) ----
    gemm_tiled<5,false,true><<<dim3(CDIV(400,64), CDIV(264,64), NI*SPLITK), 256>>>(
        w3, buf+O_C3, nullptr, part, 264, 1188, 400, (long)132*40*40, 0,
        nullptr, nullptr, 132, 40, 20, SPLITK, CDIV(1188,SPLITK));
    reduce_relu_kernel<<<CDIV(NI*264*400, TB), TB>>>(part, b3, buf+O_C4, SPLITK, 264, 400, (long)264*400);
    // ---- conv4: 264->528, 20->10 (implicit GEMM, split-K=8) ----
    gemm_tiled<5,false,true><<<dim3(CDIV(100,64), CDIV(528,64), NI*SPLITK), 256>>>(
        w4, buf+O_C4, nullptr, part, 528, 2376, 100, (long)264*20*20, 0,
        nullptr, nullptr, 264, 20, 10, SPLITK, CDIV(2376,SPLITK));
    reduce_relu_kernel<<<CDIV(NI*528*100, TB), TB>>>(part, b4, buf+O_C5, SPLITK, 528, 100, (long)528*100);

    // ---- CEM ----
    gap_kernel<<<CDIV(NI*528, TB), TB>>>(buf+O_C5, buf+O_GLB);
    gfc_kernel<<<CDIV(NI*245, TB), TB>>>(buf+O_GLB, cem_wg, cem_bg, buf+O_GFC);
    gemm_tiled<0,false,false><<<dim3(CDIV(100,64), CDIV(245,64), NI), 256>>>(
        cem_w5, buf+O_C5, cem_b5, buf+O_CEM5, 245, 528, 100,
        (long)528*100, (long)245*100, nullptr, nullptr, 0, 0, 0, 1, 528);
    gemm_tiled<3,false,false><<<dim3(CDIV(400,64), CDIV(245,64), NI), 256>>>(
        cem_w4, buf+O_C4, cem_b4, buf+O_FCEM, 245, 264, 400,
        (long)264*400, (long)245*400, buf+O_GFC, buf+O_CEM5, 0, 0, 0, 1, 264);

    // ---- RPN ----
    dw5_kernel<<<CDIV(NI*245*400, TB), TB>>>(buf+O_FCEM, rpn_dw, rpn_dwb, buf+O_T);
    gemm_tiled<1,false,false><<<dim3(CDIV(400,64), CDIV(256,64), NI), 256>>>(
        rpn_pw, buf+O_T, rpn_pwb, buf+O_FRPN, 256, 245, 400,
        (long)245*400, (long)256*400, nullptr, nullptr, 0, 0, 0, 1, 245);
    gemm_tiled<0,false,false><<<dim3(CDIV(400,64), CDIV(50,64), NI), 256>>>(
        cls_w, buf+O_FRPN, cls_b, buf+O_CLS, 50, 256, 400,
        (long)256*400, (long)50*400, nullptr, nullptr, 0, 0, 0, 1, 256);
    gemm_tiled<0,false,false><<<dim3(CDIV(400,64), CDIV(100,64), NI), 256>>>(
        reg_w, buf+O_FRPN, reg_b, buf+O_REG, 100, 256, 400,
        (long)256*400, (long)100*400, nullptr, nullptr, 0, 0, 0, 1, 256);
    gemm_tiled<2,false,false><<<dim3(CDIV(400,64), CDIV(245,64), NI), 256>>>(
        sam_w, buf+O_FRPN, sam_b, buf+O_FSAM, 245, 256, 400,
        (long)256*400, (long)245*400, buf+O_FCEM, nullptr, 0, 0, 0, 1, 256);

    // ---- proposals ----
    scorebox_kernel<<<CDIV(NI*NANCH, TB), TB>>>(buf+O_CLS, buf+O_REG, buf+O_BOX, keys);
    topk_kernel<<<NI, 1024>>>(keys, buf+O_BOX, buf+O_BK);
    nms_mask_kernel<<<dim3(NI, 125), 256>>>(buf+O_BK, mask);
    nms_scan_kernel<<<NI, 32>>>(mask, buf+O_BK, buf+O_ROI,
                                out + (size_t)NI*NROIS*21 + (size_t)NI*NROIS*4);

    // ---- head ----
    psroi_kernel<<<CDIV(NI*NROIS*245, TB), TB>>>(buf+O_FSAM, buf+O_ROI, buf+O_FROI);
    gemm_tiled<4,true,false><<<dim3(CDIV(NI*NROIS,64), CDIV(1024,64), 1), 256>>>(
        fc_w, buf+O_FROI, fc_b, buf+O_H, 1024, 245, NI*NROIS, 0, 0,
        nullptr, nullptr, 0, 0, 0, 1, 245);
    fc2_warp<<<CDIV(NI*NROIS*25*32, TB), TB>>>(buf+O_H, cls_fw, cls_fb, reg_fw, reg_fb,
                                               out, out + (size_t)NI*NROIS*21);
}

// round 13
// speedup vs baseline: 1.1921x; 1.0112x over previous
#include <cuda_runtime.h>
#include <math.h>

#define CDIV(a,b) (((a)+(b)-1)/(b))

constexpr int NI     = 8;
constexpr int NANCH  = 10000;
constexpr int PRENMS = 1000;
constexpr int NROIS  = 200;
constexpr int SPLITK = 8;

// ---- scratch layout (floats) ----
constexpr size_t O_C1  = 0;                constexpr size_t S_C1  = (size_t)NI*24*160*160;
constexpr size_t O_P1  = O_C1 + S_C1;      constexpr size_t S_P1  = (size_t)NI*24*80*80;
constexpr size_t O_C3  = O_P1 + S_P1;      constexpr size_t S_C3  = (size_t)NI*132*40*40;
constexpr size_t O_C4  = O_C3 + S_C3;      constexpr size_t S_C4  = (size_t)NI*264*20*20;
constexpr size_t O_C5  = O_C4 + S_C4;      constexpr size_t S_C5  = (size_t)NI*528*10*10;
constexpr size_t O_GLB = O_C5 + S_C5;      constexpr size_t S_GLB = (size_t)NI*528;
constexpr size_t O_GFC = O_GLB + S_GLB;    constexpr size_t S_GFC = (size_t)NI*245;
constexpr size_t O_CEM5= O_GFC + S_GFC;    constexpr size_t S_CEM5= (size_t)NI*245*100;
constexpr size_t O_FCEM= O_CEM5 + S_CEM5;  constexpr size_t S_FCEM= (size_t)NI*245*400;
constexpr size_t O_T   = O_FCEM + S_FCEM;  constexpr size_t S_T   = S_FCEM;
constexpr size_t O_FRPN= O_T + S_T;        constexpr size_t S_FRPN= (size_t)NI*256*400;
constexpr size_t O_CLS = O_FRPN + S_FRPN;  constexpr size_t S_CLS = (size_t)NI*50*400;
constexpr size_t O_REG = O_CLS + S_CLS;    constexpr size_t S_REG = (size_t)NI*100*400;
constexpr size_t O_FSAM= O_REG + S_REG;    constexpr size_t S_FSAM= S_FCEM;
constexpr size_t O_BOX = O_FSAM + S_FSAM;  constexpr size_t S_BOX = (size_t)NI*NANCH*4;
constexpr size_t O_BK  = O_BOX + S_BOX;    constexpr size_t S_BK  = (size_t)NI*PRENMS*4;
constexpr size_t O_ROI = O_BK + S_BK;      constexpr size_t S_ROI = (size_t)NI*NROIS*4;
constexpr size_t O_FROI= O_ROI + S_ROI;    constexpr size_t S_FROI= (size_t)245*NI*NROIS; // transposed [245][1600]
constexpr size_t O_H   = O_FROI + S_FROI;  constexpr size_t S_H   = (size_t)NI*NROIS*1024;
constexpr size_t O_PART= O_H + S_H;        constexpr size_t S_PART= (size_t)SPLITK*NI*264*400; // split-K partials
constexpr size_t TOTAL = O_PART + S_PART;

__device__ float g_buf[TOTAL];
__device__ unsigned long long g_keys[(size_t)NI*NANCH];
__device__ unsigned int g_mask[(size_t)NI*1024*32];

// =================== unified tiled GEMM with register-staged prefetch ===================
// 64x64 tile, 256 threads, 4x4/thread. MODE: 0 bias, 1 bias+relu, 2 fsam, 3 fcem adds,
//       4 relu + transposed store C[n][m], 5 raw partial store (split-K)
template<int MODE, bool TRANSA, bool CONV>
__global__ void __launch_bounds__(256)
gemm_tiled(const float* __restrict__ A, const float* __restrict__ B,
           const float* __restrict__ bias, float* __restrict__ C,
           int M, int K, int N, long sB, long sC,
           const float* __restrict__ e1, const float* __restrict__ e2,
           int Cin, int Hin, int Hout, int S, int kLen) {
    __shared__ float As[16][68];
    __shared__ float Bs[16][68];
    int nimg, spl;
    if (MODE == 5) { nimg = blockIdx.z / S; spl = blockIdx.z % S; }
    else           { nimg = blockIdx.z;     spl = 0; }
    int kStart = spl * kLen;
    int kEnd   = min(K, kStart + kLen);
    int m0 = blockIdx.y*64, n0 = blockIdx.x*64;
    const float* Bp = B + (long)nimg*sB;
    float* Cp = (MODE == 5) ? C + ((long)spl*NI + nimg)*M*N
                            : C + (long)nimg*sC;
    int tid = threadIdx.x;
    int tx = tid % 16, ty = tid / 16;

    float pa[4], pb[4];
    auto fetchA = [&](int kf) {
        if (!TRANSA) {
            int r = tid >> 2, c = (tid & 3) * 4;
            #pragma unroll
            for (int i = 0; i < 4; i++) {
                int mm = m0 + r, kk = kf + c + i;
                pa[i] = (mm < M && kk < kEnd) ? A[(long)mm*K + kk] : 0.f;
            }
        } else {
            int r = tid >> 4, c = (tid & 15) * 4;
            #pragma unroll
            for (int i = 0; i < 4; i++) {
                int kk = kf + r, mm = m0 + c + i;
                pa[i] = (mm < M && kk < kEnd) ? A[(long)kk*M + mm] : 0.f;
            }
        }
    };
    auto storeA = [&]() {
        if (!TRANSA) {
            int r = tid >> 2, c = (tid & 3) * 4;
            #pragma unroll
            for (int i = 0; i < 4; i++) As[c+i][r] = pa[i];
        } else {
            int r = tid >> 4, c = (tid & 15) * 4;
            #pragma unroll
            for (int i = 0; i < 4; i++) As[r][c+i] = pa[i];
        }
    };
    auto fetchB = [&](int kf) {
        int r = tid >> 4, c = (tid & 15) * 4;
        if (CONV) {
            int kk = kf + r;
            bool kv = kk < kEnd;
            int ic = 0, ky = 0, kx = 0;
            if (kv) { ic = kk / 9; int rem = kk - ic*9; ky = rem / 3; kx = rem - ky*3; }
            #pragma unroll
            for (int i = 0; i < 4; i++) {
                int nn = n0 + c + i;
                float v = 0.f;
                if (kv && nn < N) {
                    int oy = nn / Hout, ox = nn - oy*Hout;
                    int iy = 2*oy + ky, ix = 2*ox + kx;
                    if (iy < Hin && ix < Hin)
                        v = Bp[((long)ic*Hin + iy)*Hin + ix];
                }
                pb[i] = v;
            }
        } else {
            int kk = kf + r;
            #pragma unroll
            for (int i = 0; i < 4; i++) {
                int nn = n0 + c + i;
                pb[i] = (kk < kEnd && nn < N) ? Bp[(long)kk*N + nn] : 0.f;
            }
        }
    };
    auto storeB = [&]() {
        int r = tid >> 4, c = (tid & 15) * 4;
        #pragma unroll
        for (int i = 0; i < 4; i++) Bs[r][c+i] = pb[i];
    };

    float acc[4][4] = {};
    fetchA(kStart);
    fetchB(kStart);
    for (int k0 = kStart; k0 < kEnd; k0 += 16) {
        storeA();
        storeB();
        __syncthreads();
        bool has_next = (k0 + 16 < kEnd);
        if (has_next) { fetchA(k0 + 16); fetchB(k0 + 16); }
        #pragma unroll
        for (int kk = 0; kk < 16; kk++) {
            float4 av = *reinterpret_cast<const float4*>(&As[kk][ty*4]);
            float4 bv = *reinterpret_cast<const float4*>(&Bs[kk][tx*4]);
            float a[4] = {av.x, av.y, av.z, av.w};
            float b[4] = {bv.x, bv.y, bv.z, bv.w};
            #pragma unroll
            for (int i = 0; i < 4; i++)
                #pragma unroll
                for (int j = 0; j < 4; j++)
                    acc[i][j] = fmaf(a[i], b[j], acc[i][j]);
        }
        __syncthreads();
    }
    #pragma unroll
    for (int i = 0; i < 4; i++) {
        int m = m0 + ty*4 + i;
        if (m >= M) continue;
        float bv = (MODE == 5) ? 0.f : bias[m];
        #pragma unroll
        for (int j = 0; j < 4; j++) {
            int n = n0 + tx*4 + j;
            if (n >= N) continue;
            float s = acc[i][j] + bv;
            if (MODE == 1) s = fmaxf(s, 0.f);
            else if (MODE == 2) {
                s = e1[(long)nimg*sC + (long)m*N + n] * (1.f/(1.f + expf(-s)));
            } else if (MODE == 3) {
                int y = n / 20, x = n % 20;
                s += e1[nimg*245 + m] + e2[((long)nimg*245 + m)*100 + (y/2)*10 + (x/2)];
            }
            if (MODE == 4) {
                s = fmaxf(s, 0.f);
                Cp[(long)n*M + m] = s;
            } else {
                Cp[(long)m*N + n] = s;
            }
        }
    }
}

// =================== fused 3-head GEMM: cls(50) + reg(100) + sam(245), K=256, N=400 ===============
// blockIdx.y: 0 -> cls tile, 1-2 -> reg tiles, 3-6 -> sam tiles
__global__ void __launch_bounds__(256)
heads_gemm(const float* __restrict__ frpn,
           const float* __restrict__ cls_w, const float* __restrict__ cls_b,
           const float* __restrict__ reg_w, const float* __restrict__ reg_b,
           const float* __restrict__ sam_w, const float* __restrict__ sam_b,
           const float* __restrict__ fcem,
           float* __restrict__ out_cls, float* __restrict__ out_reg, float* __restrict__ out_fsam) {
    __shared__ float As[16][68];
    __shared__ float Bs[16][68];
    constexpr int K = 256, N = 400;
    int nimg = blockIdx.z;
    int tyb = blockIdx.y;
    int head, mt0;
    if (tyb < 1)      { head = 0; mt0 = 0; }
    else if (tyb < 3) { head = 1; mt0 = 1; }
    else              { head = 2; mt0 = 3; }
    const float* A  = (head == 0) ? cls_w : (head == 1) ? reg_w : sam_w;
    const float* bb = (head == 0) ? cls_b : (head == 1) ? reg_b : sam_b;
    int Mh = (head == 0) ? 50 : (head == 1) ? 100 : 245;
    int m0 = (tyb - mt0) * 64;
    int n0 = blockIdx.x * 64;
    const float* Bp = frpn + (long)nimg*K*N;
    int tid = threadIdx.x;
    int tx = tid % 16, ty = tid / 16;

    float pa[4], pb[4];
    auto fetchA = [&](int kf) {
        int r = tid >> 2, c = (tid & 3) * 4;
        #pragma unroll
        for (int i = 0; i < 4; i++) {
            int mm = m0 + r, kk = kf + c + i;
            pa[i] = (mm < Mh) ? A[(long)mm*K + kk] : 0.f;
        }
    };
    auto fetchB = [&](int kf) {
        int r = tid >> 4, c = (tid & 15) * 4;
        int kk = kf + r;
        #pragma unroll
        for (int i = 0; i < 4; i++) {
            int nn = n0 + c + i;
            pb[i] = (nn < N) ? Bp[(long)kk*N + nn] : 0.f;
        }
    };

    float acc[4][4] = {};
    fetchA(0);
    fetchB(0);
    for (int k0 = 0; k0 < K; k0 += 16) {
        {
            int r = tid >> 2, c = (tid & 3) * 4;
            #pragma unroll
            for (int i = 0; i < 4; i++) As[c+i][r] = pa[i];
        }
        {
            int r = tid >> 4, c = (tid & 15) * 4;
            #pragma unroll
            for (int i = 0; i < 4; i++) Bs[r][c+i] = pb[i];
        }
        __syncthreads();
        if (k0 + 16 < K) { fetchA(k0 + 16); fetchB(k0 + 16); }
        #pragma unroll
        for (int kk = 0; kk < 16; kk++) {
            float4 av = *reinterpret_cast<const float4*>(&As[kk][ty*4]);
            float4 bv = *reinterpret_cast<const float4*>(&Bs[kk][tx*4]);
            float a[4] = {av.x, av.y, av.z, av.w};
            float b[4] = {bv.x, bv.y, bv.z, bv.w};
            #pragma unroll
            for (int i = 0; i < 4; i++)
                #pragma unroll
                for (int j = 0; j < 4; j++)
                    acc[i][j] = fmaf(a[i], b[j], acc[i][j]);
        }
        __syncthreads();
    }
    #pragma unroll
    for (int i = 0; i < 4; i++) {
        int m = m0 + ty*4 + i;
        if (m >= Mh) continue;
        float bv = bb[m];
        #pragma unroll
        for (int j = 0; j < 4; j++) {
            int n = n0 + tx*4 + j;
            if (n >= N) continue;
            float s = acc[i][j] + bv;
            if (head == 0) {
                out_cls[((long)nimg*50 + m)*N + n] = s;
            } else if (head == 1) {
                out_reg[((long)nimg*100 + m)*N + n] = s;
            } else {
                long idx = ((long)nimg*245 + m)*N + n;
                out_fsam[idx] = fcem[idx] * (1.f/(1.f + expf(-s)));
            }
        }
    }
}

// ---- split-K reduction: out = relu(bias + sum_s partial) ----
__global__ void reduce_relu_kernel(const float* __restrict__ partial, const float* __restrict__ bias,
                                   float* __restrict__ out, int S, int M, int N, long sC) {
    int t = blockIdx.x*blockDim.x + threadIdx.x;
    int total = NI*M*N;
    if (t >= total) return;
    int nimg = t / (M*N);
    int mn   = t % (M*N);
    int m    = mn / N;
    float s = bias[m];
    for (int si = 0; si < S; si++)
        s += partial[((long)si*NI + nimg)*M*N + mn];
    out[(long)nimg*sC + mn] = fmaxf(s, 0.f);
}

// ---- split-K reduction with fcem epilogue: out = bias + gfc + up2(cem5) + sum partial ----
__global__ void reduce_fcem_kernel(const float* __restrict__ partial, const float* __restrict__ bias,
                                   const float* __restrict__ gfc, const float* __restrict__ cem5,
                                   float* __restrict__ out, int S) {
    int t = blockIdx.x*blockDim.x + threadIdx.x;
    int total = NI*245*400;
    if (t >= total) return;
    int nimg = t / (245*400);
    int mn   = t % (245*400);
    int m    = mn / 400;
    int n    = mn % 400;
    int y = n / 20, x = n % 20;
    float s = bias[m] + gfc[nimg*245 + m] + cem5[((long)nimg*245 + m)*100 + (y/2)*10 + (x/2)];
    for (int si = 0; si < S; si++)
        s += partial[((long)si*NI + nimg)*245*400 + mn];
    out[(long)nimg*245*400 + mn] = s;
}

// =================== 3x3 stride-2 maxpool SAME ===================
__global__ void maxpool3s2(const float* __restrict__ in, float* __restrict__ out,
                           int C, int Hin, int Hout) {
    int t = blockIdx.x*blockDim.x + threadIdx.x;
    int total = NI*C*Hout*Hout;
    if (t >= total) return;
    int ox = t % Hout;
    int oy = (t / Hout) % Hout;
    int nc = t / (Hout*Hout);
    const float* ip = in + (size_t)nc*Hin*Hin;
    float m = -INFINITY;
    #pragma unroll
    for (int ky = 0; ky < 3; ky++) {
        int iy = 2*oy + ky;
        if (iy >= Hin) continue;
        #pragma unroll
        for (int kx = 0; kx < 3; kx++) {
            int ix = 2*ox + kx;
            if (ix >= Hin) continue;
            m = fmaxf(m, ip[iy*Hin+ix]);
        }
    }
    out[t] = m;
}

__global__ void gap_kernel(const float* __restrict__ c5, float* __restrict__ glb) {
    int t = blockIdx.x*blockDim.x + threadIdx.x;
    if (t >= NI*528) return;
    const float* p = c5 + (size_t)t*100;
    float s = 0.f;
    for (int i = 0; i < 100; i++) s += p[i];
    glb[t] = s / 100.f;
}

__global__ void gfc_kernel(const float* __restrict__ glb, const float* __restrict__ wg,
                           const float* __restrict__ bg, float* __restrict__ gfc) {
    int t = blockIdx.x*blockDim.x + threadIdx.x;
    if (t >= NI*245) return;
    int k = t % 245, n = t / 245;
    float s = bg[k];
    const float* g = glb + n*528;
    for (int c = 0; c < 528; c++) s += g[c] * wg[c*245 + k];
    gfc[t] = s;
}

// ---- depthwise 5x5 SAME + relu ----
__global__ void dw5_kernel(const float* __restrict__ in, const float* __restrict__ w,
                           const float* __restrict__ bias, float* __restrict__ out) {
    int t = blockIdx.x*blockDim.x + threadIdx.x;
    int total = NI*245*400;
    if (t >= total) return;
    int p = t % 400;
    int k = (t / 400) % 245;
    int y = p / 20, x = p % 20;
    const float* ip = in + (size_t)(t/400)*400;
    const float* wk = w + k*25;
    float s = bias[k];
    #pragma unroll
    for (int ky = 0; ky < 5; ky++) {
        int iy = y - 2 + ky;
        if (iy < 0 || iy >= 20) continue;
        #pragma unroll
        for (int kx = 0; kx < 5; kx++) {
            int ix = x - 2 + kx;
            if (ix < 0 || ix >= 20) continue;
            s += ip[iy*20+ix] * wk[ky*5+kx];
        }
    }
    out[t] = fmaxf(s, 0.f);
}

// ---- scores + decoded boxes + sort keys ----
__global__ void scorebox_kernel(const float* __restrict__ clsmap, const float* __restrict__ regmap,
                                float* __restrict__ boxes, unsigned long long* __restrict__ keys) {
    int t = blockIdx.x*blockDim.x + threadIdx.x;
    if (t >= NI*NANCH) return;
    int i = t % NANCH;
    int n = t / NANCH;
    int a = i % 25;
    int x = (i / 25) % 20;
    int y = i / 500;
    int p = y*20 + x;
    const float* cm = clsmap + (size_t)n*50*400;
    float c0 = cm[(a*2  )*400 + p];
    float c1 = cm[(a*2+1)*400 + p];
    float score = 1.f / (1.f + expf(c0 - c1));
    const float* rm = regmap + (size_t)n*100*400;
    float d0 = rm[(a*4  )*400 + p];
    float d1 = rm[(a*4+1)*400 + p];
    float d2 = rm[(a*4+2)*400 + p];
    float d3 = rm[(a*4+3)*400 + p];
    const float scales[5] = {32.f, 64.f, 128.f, 256.f, 512.f};
    const float ratios[5] = {0.5f, 0.75f, 1.0f, 4.0f/3.0f, 2.0f};
    int si = a / 5, ri = a % 5;
    float sq = sqrtf(ratios[ri]);
    float aw = scales[si] / sq;
    float ah = scales[si] * sq;
    float acx = (x + 0.5f) * 16.f;
    float acy = (y + 0.5f) * 16.f;
    float cx = d0*aw + acx;
    float cy = d1*ah + acy;
    float w  = expf(d2) * aw;
    float h  = expf(d3) * ah;
    float* b = boxes + ((size_t)n*NANCH + i)*4;
    b[0] = fminf(fmaxf(cx - 0.5f*w, 0.f), 319.f);
    b[1] = fminf(fmaxf(cy - 0.5f*h, 0.f), 319.f);
    b[2] = fminf(fmaxf(cx + 0.5f*w, 0.f), 319.f);
    b[3] = fminf(fmaxf(cy + 0.5f*h, 0.f), 319.f);
    unsigned sb = __float_as_uint(score);  // score > 0 -> bit-monotone
    keys[t] = ((unsigned long long)sb << 32) | (unsigned long long)(0xFFFFFFFFu - (unsigned)i);
}

// ---- exact top-1000 per image: 64-bit radix select + bitonic sort of 1024 ----
__global__ void __launch_bounds__(1024)
topk_kernel(const unsigned long long* __restrict__ keys,
            const float* __restrict__ boxes, float* __restrict__ bk) {
    __shared__ unsigned int hist[256];
    __shared__ unsigned long long sh_prefix;
    __shared__ int sh_need;
    __shared__ unsigned int sh_cnt;
    __shared__ unsigned long long sk[1024];
    int n = blockIdx.x;
    int tid = threadIdx.x;
    const unsigned long long* kp = keys + (size_t)n*NANCH;

    if (tid == 0) { sh_prefix = 0ull; sh_need = PRENMS; sh_cnt = 0u; }
    __syncthreads();

    for (int shift = 56; shift >= 0; shift -= 8) {
        if (tid < 256) hist[tid] = 0u;
        __syncthreads();
        unsigned long long prefmask = (shift == 56) ? 0ull : (~0ull << (shift + 8));
        unsigned long long pref = sh_prefix;
        for (int i = tid; i < NANCH; i += 1024) {
            unsigned long long k = kp[i];
            if ((k & prefmask) == pref)
                atomicAdd(&hist[(unsigned)(k >> shift) & 255u], 1u);
        }
        __syncthreads();
        if (tid == 0) {
            int need = sh_need;
            unsigned cum = 0;
            int d = 255;
            for (; d >= 0; d--) { cum += hist[d]; if ((int)cum >= need) break; }
            sh_need = need - (int)(cum - hist[d]);
            sh_prefix = pref | ((unsigned long long)d << shift);
        }
        __syncthreads();
    }
    unsigned long long T = sh_prefix;

    if (tid < 24) sk[1000 + tid] = 0ull;
    for (int i = tid; i < NANCH; i += 1024) {
        unsigned long long k = kp[i];
        if (k >= T) sk[atomicAdd(&sh_cnt, 1u)] = k;
    }
    __syncthreads();

    for (int size = 2; size <= 1024; size <<= 1) {
        for (int stride = size >> 1; stride > 0; stride >>= 1) {
            if (tid < 512) {
                int lo = ((tid & ~(stride-1)) << 1) | (tid & (stride-1));
                int hi = lo + stride;
                unsigned long long a = sk[lo], c = sk[hi];
                bool desc = ((lo & size) == 0);
                if (desc ? (a < c) : (a > c)) { sk[lo] = c; sk[hi] = a; }
            }
            __syncthreads();
        }
    }

    if (tid < PRENMS) {
        unsigned idx = 0xFFFFFFFFu - (unsigned)(sk[tid] & 0xFFFFFFFFull);
        const float* src = boxes + ((size_t)n*NANCH + idx)*4;
        float* dst = bk + ((size_t)n*PRENMS + tid)*4;
        dst[0] = src[0]; dst[1] = src[1]; dst[2] = src[2]; dst[3] = src[3];
    }
}

// ---- suppression bitmask ----
__global__ void __launch_bounds__(256)
nms_mask_kernel(const float* __restrict__ bk, unsigned int* __restrict__ mask) {
    __shared__ float4 box[PRENMS];
    __shared__ float  area[PRENMS];
    int n = blockIdx.x;
    int i0 = blockIdx.y * 8;
    int tid = threadIdx.x;
    const float* b = bk + (size_t)n*PRENMS*4;
    for (int i = tid; i < PRENMS; i += 256) {
        float x1 = b[i*4], y1 = b[i*4+1], x2 = b[i*4+2], y2 = b[i*4+3];
        box[i] = make_float4(x1, y1, x2, y2);
        area[i] = (x2-x1)*(y2-y1);
    }
    __syncthreads();
    int w  = tid & 31;
    int il = tid >> 5;
    int i = i0 + il;
    if (i >= PRENMS) return;
    float4 bi = box[i];
    float ai = area[i];
    unsigned m = 0u;
    int jbase = w * 32;
    #pragma unroll 4
    for (int bbit = 0; bbit < 32; bbit++) {
        int j = jbase + bbit;
        if (j > i && j < PRENMS) {
            float ix1 = fmaxf(bi.x, box[j].x);
            float iy1 = fmaxf(bi.y, box[j].y);
            float ix2 = fminf(bi.z, box[j].z);
            float iy2 = fminf(bi.w, box[j].w);
            float inter = fmaxf(ix2-ix1, 0.f) * fmaxf(iy2-iy1, 0.f);
            float iou = inter / (ai + area[j] - inter + 1e-9f);
            if (iou > 0.7f) m |= (1u << bbit);
        }
    }
    mask[((size_t)n*1024 + i)*32 + w] = m;
}

// ---- single-warp NMS scan + stable partition -> 200 rois ----
__global__ void __launch_bounds__(32)
nms_scan_kernel(const unsigned int* __restrict__ mask, const float* __restrict__ bk,
                float* __restrict__ rois, float* __restrict__ out_rois) {
    __shared__ unsigned char keep[PRENMS];
    __shared__ int order[NROIS];
    int n = blockIdx.x;
    int lane = threadIdx.x;
    const unsigned int* mp = mask + (size_t)n*1024*32;
    unsigned removed = 0u;
    unsigned next_m = mp[0*32 + lane];
    for (int i = 0; i < PRENMS; i++) {
        unsigned m = next_m;
        if (i + 1 < PRENMS) next_m = mp[(i+1)*32 + lane];
        unsigned rw = __shfl_sync(0xFFFFFFFFu, removed, i >> 5);
        bool keep_i = ((rw >> (i & 31)) & 1u) == 0u;
        if (keep_i) removed |= m;
        if (lane == 0) keep[i] = keep_i ? 1 : 0;
    }
    __syncwarp();
    if (lane == 0) {
        int c = 0;
        for (int i = 0; i < PRENMS && c < NROIS; i++) if (keep[i])  order[c++] = i;
        for (int i = 0; i < PRENMS && c < NROIS; i++) if (!keep[i]) order[c++] = i;
    }
    __syncwarp();
    const float* b = bk + (size_t)n*PRENMS*4;
    for (int r = lane; r < NROIS; r += 32) {
        int idx = order[r];
        float x1 = b[idx*4], y1 = b[idx*4+1], x2 = b[idx*4+2], y2 = b[idx*4+3];
        float* dst = rois + ((size_t)n*NROIS + r)*4;
        dst[0] = x1; dst[1] = y1; dst[2] = x2; dst[3] = y2;
        float* o = out_rois + ((size_t)n*NROIS + r)*4;
        o[0] = x1; o[1] = y1; o[2] = x2; o[3] = y2;
    }
}

// ---- PSRoI pooling: stores TRANSPOSED froiT[c][n*200+r] for fc1 GEMM ----
__global__ void psroi_kernel(const float* __restrict__ fsam, const float* __restrict__ rois,
                             float* __restrict__ froiT) {
    int t = blockIdx.x*blockDim.x + threadIdx.x;
    int total = NI*NROIS*245;
    if (t >= total) return;
    int c = t % 245;
    int r = (t / 245) % NROIS;
    int n = t / (245*NROIS);
    const float* ro = rois + ((size_t)n*NROIS + r)*4;
    float x1 = ro[0] * (1.f/16.f), y1 = ro[1] * (1.f/16.f);
    float x2 = ro[2] * (1.f/16.f), y2 = ro[3] * (1.f/16.f);
    float bw = fmaxf(x2-x1, 0.1f) * (1.f/7.f);
    float bh = fmaxf(y2-y1, 0.1f) * (1.f/7.f);
    int ij = c % 49;
    int i = ij / 7, j = ij % 7;
    float sx = x1 + (j + 0.5f) * bw;
    float sy = y1 + (i + 0.5f) * bh;
    float x = fminf(fmaxf(sx, 0.f), 19.f);
    float y = fminf(fmaxf(sy, 0.f), 19.f);
    int y0 = min(max((int)floorf(y), 0), 18);
    int x0 = min(max((int)floorf(x), 0), 18);
    float wy = y - (float)y0;
    float wx = x - (float)x0;
    const float* f = fsam + ((size_t)n*245 + c)*400;
    float v00 = f[y0*20 + x0],     v01 = f[y0*20 + x0 + 1];
    float v10 = f[(y0+1)*20 + x0], v11 = f[(y0+1)*20 + x0 + 1];
    float v = v00*(1.f-wy)*(1.f-wx) + v01*(1.f-wy)*wx + v10*wy*(1.f-wx) + v11*wy*wx;
    froiT[(size_t)c*(NI*NROIS) + (size_t)n*NROIS + r] = v;
}

// ---- FC2 heads: one warp per (row, output) ----
__global__ void __launch_bounds__(256)
fc2_warp(const float* __restrict__ h, const float* __restrict__ cfw,
         const float* __restrict__ cfb, const float* __restrict__ rfw,
         const float* __restrict__ rfb, float* __restrict__ out_cls,
         float* __restrict__ out_reg) {
    int w = (blockIdx.x*blockDim.x + threadIdx.x) >> 5;
    int lane = threadIdx.x & 31;
    if (w >= NI*NROIS*25) return;
    int m = w % 25;
    int row = w / 25;
    const float* hr = h + (size_t)row*1024;
    float s = 0.f;
    if (m < 21) {
        for (int k = lane; k < 1024; k += 32) s = fmaf(hr[k], cfw[k*21 + m], s);
    } else {
        int mm = m - 21;
        for (int k = lane; k < 1024; k += 32) s = fmaf(hr[k], rfw[k*4 + mm], s);
    }
    #pragma unroll
    for (int o = 16; o > 0; o >>= 1) s += __shfl_down_sync(0xFFFFFFFFu, s, o);
    if (lane == 0) {
        if (m < 21) out_cls[row*21 + m] = s + cfb[m];
        else        out_reg[row*4 + (m-21)] = s + rfb[m-21];
    }
}

extern "C" void kernel_launch(void* const* d_in, const int* in_sizes, int n_in,
                              void* d_out, int out_size) {
    const float* x      = (const float*)d_in[0];
    const float* w1     = (const float*)d_in[1];
    const float* b1     = (const float*)d_in[2];
    const float* w2     = (const float*)d_in[3];
    const float* b2     = (const float*)d_in[4];
    const float* w3     = (const float*)d_in[5];
    const float* b3     = (const float*)d_in[6];
    const float* w4     = (const float*)d_in[7];
    const float* b4     = (const float*)d_in[8];
    const float* cem_w4 = (const float*)d_in[9];
    const float* cem_b4 = (const float*)d_in[10];
    const float* cem_w5 = (const float*)d_in[11];
    const float* cem_b5 = (const float*)d_in[12];
    const float* cem_wg = (const float*)d_in[13];
    const float* cem_bg = (const float*)d_in[14];
    const float* rpn_dw = (const float*)d_in[15];
    const float* rpn_dwb= (const float*)d_in[16];
    const float* rpn_pw = (const float*)d_in[17];
    const float* rpn_pwb= (const float*)d_in[18];
    const float* cls_w  = (const float*)d_in[19];
    const float* cls_b  = (const float*)d_in[20];
    const float* reg_w  = (const float*)d_in[21];
    const float* reg_b  = (const float*)d_in[22];
    const float* sam_w  = (const float*)d_in[23];
    const float* sam_b  = (const float*)d_in[24];
    const float* fc_w   = (const float*)d_in[25];
    const float* fc_b   = (const float*)d_in[26];
    const float* cls_fw = (const float*)d_in[27];
    const float* cls_fb = (const float*)d_in[28];
    const float* reg_fw = (const float*)d_in[29];
    const float* reg_fb = (const float*)d_in[30];
    float* out = (float*)d_out;

    float* buf = nullptr;
    cudaGetSymbolAddress((void**)&buf, g_buf);
    unsigned long long* keys = nullptr;
    cudaGetSymbolAddress((void**)&keys, g_keys);
    unsigned int* mask = nullptr;
    cudaGetSymbolAddress((void**)&mask, g_mask);

    const int TB = 256;
    float* part = buf + O_PART;

    // ---- conv1: 3->24, 320->160 (implicit GEMM) ----
    gemm_tiled<1,false,true><<<dim3(CDIV(25600,64), 1, NI), 256>>>(
        w1, x, b1, buf+O_C1, 24, 27, 25600, (long)3*320*320, (long)24*25600,
        nullptr, nullptr, 3, 320, 160, 1, 27);
    maxpool3s2<<<CDIV(NI*24*80*80, TB), TB>>>(buf+O_C1, buf+O_P1, 24, 160, 80);
    // ---- conv2: 24->132, 80->40 (implicit GEMM) ----
    gemm_tiled<1,false,true><<<dim3(CDIV(1600,64), CDIV(132,64), NI), 256>>>(
        w2, buf+O_P1, b2, buf+O_C3, 132, 216, 1600, (long)24*80*80, (long)132*1600,
        nullptr, nullptr, 24, 80, 40, 1, 216);
    // ---- conv3: 132->264, 40->20 (implicit GEMM, split-K=8) ----
    gemm_tiled<5,false,true><<<dim3(CDIV(400,64), CDIV(264,64), NI*SPLITK), 256>>>(
        w3, buf+O_C3, nullptr, part, 264, 1188, 400, (long)132*40*40, 0,
        nullptr, nullptr, 132, 40, 20, SPLITK, CDIV(1188,SPLITK));
    reduce_relu_kernel<<<CDIV(NI*264*400, TB), TB>>>(part, b3, buf+O_C4, SPLITK, 264, 400, (long)264*400);
    // ---- conv4: 264->528, 20->10 (implicit GEMM, split-K=8) ----
    gemm_tiled<5,false,true><<<dim3(CDIV(100,64), CDIV(528,64), NI*SPLITK), 256>>>(
        w4, buf+O_C4, nullptr, part, 528, 2376, 100, (long)264*20*20, 0,
        nullptr, nullptr, 264, 20, 10, SPLITK, CDIV(2376,SPLITK));
    reduce_relu_kernel<<<CDIV(NI*528*100, TB), TB>>>(part, b4, buf+O_C5, SPLITK, 528, 100, (long)528*100);

    // ---- CEM ----
    gap_kernel<<<CDIV(NI*528, TB), TB>>>(buf+O_C5, buf+O_GLB);
    gfc_kernel<<<CDIV(NI*245, TB), TB>>>(buf+O_GLB, cem_wg, cem_bg, buf+O_GFC);
    gemm_tiled<0,false,false><<<dim3(CDIV(100,64), CDIV(245,64), NI), 256>>>(
        cem_w5, buf+O_C5, cem_b5, buf+O_CEM5, 245, 528, 100,
        (long)528*100, (long)245*100, nullptr, nullptr, 0, 0, 0, 1, 528);
    // cem_w4 1x1: split-K=4 -> partials, then fcem reduce with gfc/up2 adds
    gemm_tiled<5,false,false><<<dim3(CDIV(400,64), CDIV(245,64), NI*4), 256>>>(
        cem_w4, buf+O_C4, nullptr, part, 245, 264, 400,
        (long)264*400, 0, nullptr, nullptr, 0, 0, 0, 4, CDIV(264,4));
    reduce_fcem_kernel<<<CDIV(NI*245*400, TB), TB>>>(part, cem_b4, buf+O_GFC, buf+O_CEM5,
                                                     buf+O_FCEM, 4);

    // ---- RPN ----
    dw5_kernel<<<CDIV(NI*245*400, TB), TB>>>(buf+O_FCEM, rpn_dw, rpn_dwb, buf+O_T);
    // rpn_pw 1x1: split-K=4 -> partials, then relu reduce
    gemm_tiled<5,false,false><<<dim3(CDIV(400,64), CDIV(256,64), NI*4), 256>>>(
        rpn_pw, buf+O_T, nullptr, part, 256, 245, 400,
        (long)245*400, 0, nullptr, nullptr, 0, 0, 0, 4, CDIV(245,4));
    reduce_relu_kernel<<<CDIV(NI*256*400, TB), TB>>>(part, rpn_pwb, buf+O_FRPN, 4, 256, 400, (long)256*400);
    // fused heads: cls + reg + sam(->fsam) in one launch
    heads_gemm<<<dim3(7, 7, NI), 256>>>(buf+O_FRPN, cls_w, cls_b, reg_w, reg_b,
                                        sam_w, sam_b, buf+O_FCEM,
                                        buf+O_CLS, buf+O_REG, buf+O_FSAM);

    // ---- proposals ----
    scorebox_kernel<<<CDIV(NI*NANCH, TB), TB>>>(buf+O_CLS, buf+O_REG, buf+O_BOX, keys);
    topk_kernel<<<NI, 1024>>>(keys, buf+O_BOX, buf+O_BK);
    nms_mask_kernel<<<dim3(NI, 125), 256>>>(buf+O_BK, mask);
    nms_scan_kernel<<<NI, 32>>>(mask, buf+O_BK, buf+O_ROI,
                                out + (size_t)NI*NROIS*21 + (size_t)NI*NROIS*4);

    // ---- head ----
    psroi_kernel<<<CDIV(NI*NROIS*245, TB), TB>>>(buf+O_FSAM, buf+O_ROI, buf+O_FROI);
    gemm_tiled<4,true,false><<<dim3(CDIV(NI*NROIS,64), CDIV(1024,64), 1), 256>>>(
        fc_w, buf+O_FROI, fc_b, buf+O_H, 1024, 245, NI*NROIS, 0, 0,
        nullptr, nullptr, 0, 0, 0, 1, 245);
    fc2_warp<<<CDIV(NI*NROIS*25*32, TB), TB>>>(buf+O_H, cls_fw, cls_fb, reg_fw, reg_fb,
                                               out, out + (size_t)NI*NROIS*21);
}